// round 14
// baseline (speedup 1.0000x reference)
#include <cuda_runtime.h>
#include <cstdint>

#define BB 2
#define NN 2048
#define DD 1024
#define HH 16
#define HD 64
typedef unsigned short u16;
typedef uint32_t u32;

__device__ __align__(16) u16 g_xh[(size_t)BB*NN*DD];
__device__ __align__(16) u16 g_xl[(size_t)BB*NN*DD];
__device__ __align__(16) u16 g_wh[4][(size_t)DD*DD];
__device__ __align__(16) u16 g_wl[4][(size_t)DD*DD];
__device__ __align__(16) u16 g_qh[(size_t)BB*HH*NN*HD];
__device__ __align__(16) u16 g_ql[(size_t)BB*HH*NN*HD];
__device__ __align__(16) u16 g_kh[(size_t)BB*HH*NN*HD];
__device__ __align__(16) u16 g_kl[(size_t)BB*HH*NN*HD];
__device__ __align__(16) u16 g_vh[(size_t)BB*HH*NN*HD];   // fp16 planes
__device__ __align__(16) u16 g_vl[(size_t)BB*HH*NN*HD];
__device__ __align__(16) u16 g_cth[(size_t)BB*NN*DD];
__device__ __align__(16) u16 g_ctl[(size_t)BB*NN*DD];

__device__ __forceinline__ void bsplit(float x, u16 &h, u16 &l){
    asm("cvt.rn.bf16.f32 %0, %1;" : "=h"(h) : "f"(x));
    float hf = __uint_as_float((u32)h << 16);
    asm("cvt.rn.bf16.f32 %0, %1;" : "=h"(l) : "f"(x - hf));
}
__device__ __forceinline__ void hsplit(float x, u16 &h, u16 &l){
    asm("cvt.rn.f16.f32 %0, %1;" : "=h"(h) : "f"(x));
    float hf; asm("cvt.f32.f16 %0, %1;" : "=f"(hf) : "h"(h));
    asm("cvt.rn.f16.f32 %0, %1;" : "=h"(l) : "f"(x - hf));
}
__device__ __forceinline__ u32 packh(float lo, float hi){
    u32 r; asm("cvt.rn.f16x2.f32 %0, %1, %2;" : "=r"(r) : "f"(hi), "f"(lo));
    return r;
}
__device__ __forceinline__ float ex2f(float x){
    float r; asm("ex2.approx.ftz.f32 %0, %1;" : "=f"(r) : "f"(x));
    return r;
}
__device__ __forceinline__ float lg2f(float x){
    float r; asm("lg2.approx.ftz.f32 %0, %1;" : "=f"(r) : "f"(x));
    return r;
}
__device__ __forceinline__ u32 smem_u32(const void* p){
    u32 a;
    asm("{ .reg .u64 t; cvta.to.shared.u64 t, %1; cvt.u32.u64 %0, t; }" : "=r"(a) : "l"(p));
    return a;
}
__device__ __forceinline__ void cpa16(u32 dst, const void* src){
    asm volatile("cp.async.cg.shared.global [%0], [%1], 16;" :: "r"(dst), "l"(src));
}
__device__ __forceinline__ void cpa_commit(){ asm volatile("cp.async.commit_group;" ::: "memory"); }
__device__ __forceinline__ void cpa_wait0(){ asm volatile("cp.async.wait_group 0;" ::: "memory"); }
__device__ __forceinline__ void cpa_wait1(){ asm volatile("cp.async.wait_group 1;" ::: "memory"); }

__device__ __forceinline__ void ldmx4(u32* r, u32 a){
    asm volatile("ldmatrix.sync.aligned.m8n8.x4.shared.b16 {%0,%1,%2,%3}, [%4];"
        : "=r"(r[0]), "=r"(r[1]), "=r"(r[2]), "=r"(r[3]) : "r"(a));
}
__device__ __forceinline__ void ldmx4t(u32* r, u32 a){
    asm volatile("ldmatrix.sync.aligned.m8n8.x4.trans.shared.b16 {%0,%1,%2,%3}, [%4];"
        : "=r"(r[0]), "=r"(r[1]), "=r"(r[2]), "=r"(r[3]) : "r"(a));
}
__device__ __forceinline__ void mmab(float4& d, const u32* a, u32 b0, u32 b1){
    asm volatile("mma.sync.aligned.m16n8k16.row.col.f32.bf16.bf16.f32 "
        "{%0,%1,%2,%3},{%4,%5,%6,%7},{%8,%9},{%0,%1,%2,%3};"
        : "+f"(d.x), "+f"(d.y), "+f"(d.z), "+f"(d.w)
        : "r"(a[0]), "r"(a[1]), "r"(a[2]), "r"(a[3]), "r"(b0), "r"(b1));
}
__device__ __forceinline__ void mmah(float4& d, const u32* a, u32 b0, u32 b1){
    asm volatile("mma.sync.aligned.m16n8k16.row.col.f32.f16.f16.f32 "
        "{%0,%1,%2,%3},{%4,%5,%6,%7},{%8,%9},{%0,%1,%2,%3};"
        : "+f"(d.x), "+f"(d.y), "+f"(d.z), "+f"(d.w)
        : "r"(a[0]), "r"(a[1]), "r"(a[2]), "r"(a[3]), "r"(b0), "r"(b1));
}
__device__ __forceinline__ void mma3b(float4& d, const u32* ah, const u32* al,
                                      const u32* bh, const u32* bl, int ng){
    mmab(d, ah, bh[2*ng], bh[2*ng+1]);
    mmab(d, ah, bl[2*ng], bl[2*ng+1]);
    mmab(d, al, bh[2*ng], bh[2*ng+1]);
}
__device__ __forceinline__ void mma2h(float4& d, const u32* ah,
                                      const u32* bh, const u32* bl, int ng){
    mmah(d, ah, bh[2*ng], bh[2*ng+1]);
    mmah(d, ah, bl[2*ng], bl[2*ng+1]);
}

// ============================================================
// presplit (single launch)
// ============================================================
__device__ __forceinline__ void dosplit4(const float4* src, ushort4* hi, ushort4* lo, int i){
    float4 v = src[i];
    u16 h0,l0,h1,l1,h2,l2,h3,l3;
    bsplit(v.x,h0,l0); bsplit(v.y,h1,l1); bsplit(v.z,h2,l2); bsplit(v.w,h3,l3);
    hi[i] = make_ushort4(h0,h1,h2,h3);
    lo[i] = make_ushort4(l0,l1,l2,l3);
}
__global__ __launch_bounds__(256) void presplitAll(const float4* __restrict__ x,
                                                   const float4* __restrict__ Wq,
                                                   const float4* __restrict__ Wk,
                                                   const float4* __restrict__ Wv,
                                                   const float4* __restrict__ Wo){
    int bid = blockIdx.x;
    if (bid < 4096) {
        dosplit4(x, (ushort4*)g_xh, (ushort4*)g_xl, bid * 256 + threadIdx.x);
    } else {
        int m = (bid - 4096) >> 10;
        int i = ((bid - 4096) & 1023) * 256 + threadIdx.x;
        const float4* src = (m == 0) ? Wq : (m == 1) ? Wk : (m == 2) ? Wv : Wo;
        dosplit4(src, (ushort4*)g_wh[m], (ushort4*)g_wl[m], i);
    }
}

// ============================================================
// GEMM core (unchanged R13)
// ============================================================
#define GPL 8192u
#define GSTG 32768u

__device__ __forceinline__ void g_issue(u32 st,
        const u16* __restrict__ Ah, const u16* __restrict__ Al,
        const u16* __restrict__ Bh, const u16* __restrict__ Bl,
        int m0, int n0, int k0, int tid){
#pragma unroll
    for (int i = 0; i < 8; i++) {
        int idx = tid + i * 256;
        int p = idx >> 9, q = idx & 511;
        int r = q >> 2, c = q & 3;
        u32 sa = st + (u32)p * GPL + (u32)(r * 64 + ((c * 16) ^ (((r >> 1) & 3) << 4)));
        const u16* g = (p == 0) ? Ah : (p == 1) ? Al : (p == 2) ? Bh : Bl;
        int rb = (p < 2) ? m0 : n0;
        cpa16(sa, g + (size_t)(rb + r) * DD + k0 + c * 8);
    }
}

__device__ __forceinline__ void g_run(const u16* Ah, const u16* Al, const u16* Bh, const u16* Bl,
                                      char* sm, int m0, int n0, int tid,
                                      float4 (&acc)[2][8], int wm, int wn, int lane){
    u32 sb = smem_u32(sm);
    const int arow = wm * 32 + (lane & 7) + 8 * ((lane >> 3) & 1);
    const int brow = wn * 64 + (lane & 7) + 8 * ((lane >> 4) & 1);
    const u32 axm = ((((lane & 7) >> 1) & 3) << 4);
    const u32 bxm = axm;
    const u32 aB = sb + (u32)(arow * 64);
    const u32 bB = sb + 2u * GPL + (u32)(brow * 64);
    const u32 a16 = 16u * (u32)(lane >> 4);
    const u32 b16 = 16u * (u32)((lane >> 3) & 1);

    g_issue(sb,        Ah, Al, Bh, Bl, m0, n0, 0,  tid); cpa_commit();
    g_issue(sb + GSTG, Ah, Al, Bh, Bl, m0, n0, 32, tid); cpa_commit();
    for (int it = 0; it < 32; it++) {
        u32 so = (u32)(it % 3) * GSTG;
        if (it < 31) cpa_wait1(); else cpa_wait0();
        __syncthreads();
        if (it + 2 < 32) {
            g_issue(sb + (u32)((it + 2) % 3) * GSTG, Ah, Al, Bh, Bl, m0, n0, (it + 2) * 32, tid);
            cpa_commit();
        }
#pragma unroll
        for (int kk = 0; kk < 2; kk++) {
            u32 ah4[2][4], al4[2][4];
            u32 ao = ((u32)(kk * 32) + a16) ^ axm;
#pragma unroll
            for (int mt = 0; mt < 2; mt++) {
                ldmx4(ah4[mt], aB + so + (u32)(mt * 1024) + ao);
                ldmx4(al4[mt], aB + so + GPL + (u32)(mt * 1024) + ao);
            }
            u32 bo = ((u32)(kk * 32) + b16) ^ bxm;
#pragma unroll
            for (int ntp = 0; ntp < 4; ntp++) {
                u32 bh4[4], bl4[4];
                ldmx4(bh4, bB + so + (u32)(ntp * 1024) + bo);
                ldmx4(bl4, bB + so + GPL + (u32)(ntp * 1024) + bo);
#pragma unroll
                for (int mt = 0; mt < 2; mt++) {
                    mma3b(acc[mt][ntp*2+0], ah4[mt], al4[mt], bh4, bl4, 0);
                    mma3b(acc[mt][ntp*2+1], ah4[mt], al4[mt], bh4, bl4, 1);
                }
            }
        }
    }
}

__global__ __launch_bounds__(256, 2) void gemm_qkv(void)
{
    extern __shared__ char gsm[];
    const int tid = threadIdx.x, lane = tid & 31, wid = tid >> 5;
    const int g = lane >> 2, t = lane & 3;
    const int wm = wid >> 1, wn = wid & 1;

    for (int tile = blockIdx.x; tile < 768; tile += gridDim.x) {
        const int mat = tile >> 8, rem = tile & 255;
        const int m0 = (rem >> 3) * 128, n0 = (rem & 7) * 128;
        const u16 *Bh = g_wh[mat], *Bl = g_wl[mat];
        u16 *Ch, *Cl;
        if (mat == 0) { Ch = g_qh; Cl = g_ql; }
        else if (mat == 1) { Ch = g_kh; Cl = g_kl; }
        else { Ch = g_vh; Cl = g_vl; }

        float4 acc[2][8];
#pragma unroll
        for (int i = 0; i < 2; i++)
#pragma unroll
            for (int j = 0; j < 8; j++) acc[i][j] = make_float4(0.f,0.f,0.f,0.f);

        __syncthreads();
        g_run(g_xh, g_xl, Bh, Bl, gsm, m0, n0, tid, acc, wm, wn, lane);

#pragma unroll
        for (int mt = 0; mt < 2; mt++) {
            int r0 = m0 + wm * 32 + mt * 16 + g;
#pragma unroll
            for (int nt = 0; nt < 8; nt++) {
                int n = n0 + wn * 64 + nt * 8 + 2 * t;
                int h = n >> 6, cc = n & 63;
                float4 c = acc[mt][nt];
                int b0r = r0 >> 11, i0r = r0 & (NN - 1);
                int b1r = (r0 + 8) >> 11, i1r = (r0 + 8) & (NN - 1);
                size_t i0 = ((size_t)(b0r * HH + h) * NN + i0r) * HD + cc;
                size_t i1 = ((size_t)(b1r * HH + h) * NN + i1r) * HD + cc;
                u16 h0,l0,h1,l1;
                if (mat == 2) {
                    hsplit(c.x,h0,l0); hsplit(c.y,h1,l1);
                    *(ushort2*)&Ch[i0] = make_ushort2(h0,h1);
                    *(ushort2*)&Cl[i0] = make_ushort2(l0,l1);
                    hsplit(c.z,h0,l0); hsplit(c.w,h1,l1);
                    *(ushort2*)&Ch[i1] = make_ushort2(h0,h1);
                    *(ushort2*)&Cl[i1] = make_ushort2(l0,l1);
                } else {
                    bsplit(c.x,h0,l0); bsplit(c.y,h1,l1);
                    *(ushort2*)&Ch[i0] = make_ushort2(h0,h1);
                    *(ushort2*)&Cl[i0] = make_ushort2(l0,l1);
                    bsplit(c.z,h0,l0); bsplit(c.w,h1,l1);
                    *(ushort2*)&Ch[i1] = make_ushort2(h0,h1);
                    *(ushort2*)&Cl[i1] = make_ushort2(l0,l1);
                }
            }
        }
    }
}

__global__ __launch_bounds__(256, 2) void gemm_out(const float* __restrict__ bias,
                                                   float* __restrict__ C)
{
    extern __shared__ char gsm[];
    const int tid = threadIdx.x, lane = tid & 31, wid = tid >> 5;
    const int g = lane >> 2, t = lane & 3;
    const int wm = wid >> 1, wn = wid & 1;
    const int m0 = blockIdx.y * 128, n0 = blockIdx.x * 128;

    float4 acc[2][8];
#pragma unroll
    for (int i = 0; i < 2; i++)
#pragma unroll
        for (int j = 0; j < 8; j++) acc[i][j] = make_float4(0.f,0.f,0.f,0.f);

    g_run(g_cth, g_ctl, g_wh[3], g_wl[3], gsm, m0, n0, tid, acc, wm, wn, lane);

#pragma unroll
    for (int mt = 0; mt < 2; mt++) {
        int r0 = m0 + wm * 32 + mt * 16 + g;
#pragma unroll
        for (int nt = 0; nt < 8; nt++) {
            int n = n0 + wn * 64 + nt * 8 + 2 * t;
            float bx = bias[n], by = bias[n + 1];
            float4 c = acc[mt][nt];
            *(float2*)&C[(size_t)r0 * DD + n]       = make_float2(c.x + bx, c.y + by);
            *(float2*)&C[(size_t)(r0 + 8) * DD + n] = make_float2(c.z + bx, c.w + by);
        }
    }
}

// ============================================================
// Attention: single fused flash pass (online max, fp16 PV),
// conditional pass B (QK recompute) only where beta != 1.
// No S cache.
// ============================================================
#define ARS 144
#define AQPL 18432u
#define AKPL 9216u
#define AK_OFF 36864u
#define ABF 36864u      // one buffer: Kh,Kl,Vh,Vl
#define ASMEM 110592
#define SCL 0.180336880f
#define LN2 0.693147181f

__device__ __forceinline__ void a_issueKV(u32 bufBase,
        const u16* __restrict__ Kh, const u16* __restrict__ Kl,
        const u16* __restrict__ Vh, const u16* __restrict__ Vl, int row0, int tid){
#pragma unroll
    for (int i = 0; i < 8; i++) {
        int idx = tid + i * 256;
        int p = idx >> 9, q = idx & 511;
        int r = q >> 3, c = q & 7;
        u32 sa = bufBase + (u32)p * AKPL + (u32)(r * ARS + c * 16);
        const u16* g = (p == 0) ? Kh : (p == 1) ? Kl : (p == 2) ? Vh : Vl;
        cpa16(sa, g + (size_t)(row0 + r) * HD + c * 8);
    }
}

__device__ __forceinline__ void qk_tile(float4 (&s)[8], u32 qBase, u32 kb){
#pragma unroll
    for (int nt = 0; nt < 8; nt++) s[nt] = make_float4(0.f,0.f,0.f,0.f);
#pragma unroll
    for (int kk = 0; kk < 4; kk++) {
        u32 qh4[4], ql4[4];
        ldmx4(qh4, qBase + (u32)(kk * 32));
        ldmx4(ql4, qBase + AQPL + (u32)(kk * 32));
#pragma unroll
        for (int ntp = 0; ntp < 4; ntp++) {
            u32 bh4[4], bl4[4];
            ldmx4(bh4, kb + (u32)(ntp * 2304 + kk * 32));
            ldmx4(bl4, kb + AKPL + (u32)(ntp * 2304 + kk * 32));
            mma3b(s[ntp*2+0], qh4, ql4, bh4, bl4, 0);
            mma3b(s[ntp*2+1], qh4, ql4, bh4, bl4, 1);
        }
    }
}

__global__ __launch_bounds__(256, 2) void attn_mma(void)
{
    extern __shared__ char sm[];
    __shared__ int sflags[8];
    u32 sb = smem_u32(sm);

    const int tid = threadIdx.x, lane = tid & 31, wid = tid >> 5;
    const int g = lane >> 2, t = lane & 3;
    const int qt = 15 - (int)(blockIdx.x >> 5);
    const int bh = blockIdx.x & 31;
    const int h = bh >> 1, b = bh & 1;
    const int q0 = qt * 128, ktmax = 2 * qt + 1;
    const size_t ho = (size_t)(b * HH + h) * NN * HD;
    const u16 *Qh = g_qh + ho, *Ql = g_ql + ho;
    const u16 *Kh = g_kh + ho, *Kl = g_kl + ho;
    const u16 *Vh = g_vh + ho, *Vl = g_vl + ho;

    const int wr = wid * 16;
    const int gr0 = q0 + wr + g, gr1 = gr0 + 8;

    const u32 qBase = sb + (u32)((wr + (lane & 7) + 8 * ((lane >> 3) & 1)) * ARS + 16 * (lane >> 4));
    const u32 kOff = (u32)(((lane & 7) + 8 * ((lane >> 4) & 1)) * ARS + 16 * ((lane >> 3) & 1));
    const u32 vOff = (u32)(((lane & 7) + 8 * ((lane >> 3) & 1)) * ARS + 16 * (lane >> 4));

#pragma unroll
    for (int i = 0; i < 8; i++) {
        int p = i >> 2;
        int rem = tid + (i & 3) * 256;
        int r = rem >> 3, c = rem & 7;
        u32 sa = sb + (u32)p * AQPL + (u32)(r * ARS + c * 16);
        const u16* gq = p ? Ql : Qh;
        cpa16(sa, gq + (size_t)(q0 + r) * HD + c * 8);
    }
    a_issueKV(sb + AK_OFF, Kh, Kl, Vh, Vl, 0, tid);
    cpa_commit();

    float mr[2] = {-1e4f, -1e4f}, se[2] = {0.f, 0.f}, st[2] = {0.f, 0.f};
    float4 o[8];
#pragma unroll
    for (int nt = 0; nt < 8; nt++) o[nt] = make_float4(0.f,0.f,0.f,0.f);

    // ===== fused pass: QK, online stats, PV =====
    for (int kt = 0; kt <= ktmax; kt++) {
        int ktb = kt * 64;
        bool act = (ktb <= q0 + wr + 15);
        cpa_wait0();
        __syncthreads();
        if (kt < ktmax) {
            a_issueKV(sb + AK_OFF + (u32)((kt + 1) & 1) * ABF, Kh, Kl, Vh, Vl, ktb + 64, tid);
            cpa_commit();
        }
        if (act) {
            u32 kb = sb + AK_OFF + (u32)(kt & 1) * ABF + kOff;
            u32 vb = sb + AK_OFF + (u32)(kt & 1) * ABF + 2u * AKPL + vOff;
            float4 s[8];
            qk_tile(s, qBase, kb);
            // mask + scale in place, tile max
            float cm0 = -1e30f, cm1 = -1e30f;
#pragma unroll
            for (int nt = 0; nt < 8; nt++) {
                int gc = ktb + nt * 8 + 2 * t;
                float a0 = (gc     <= gr0) ? s[nt].x * SCL : -1e30f;
                float a1 = (gc + 1 <= gr0) ? s[nt].y * SCL : -1e30f;
                float b0 = (gc     <= gr1) ? s[nt].z * SCL : -1e30f;
                float b1 = (gc + 1 <= gr1) ? s[nt].w * SCL : -1e30f;
                s[nt] = make_float4(a0, a1, b0, b1);
                cm0 = fmaxf(cm0, fmaxf(a0, a1));
                cm1 = fmaxf(cm1, fmaxf(b0, b1));
            }
            cm0 = fmaxf(cm0, __shfl_xor_sync(0xffffffffu, cm0, 1));
            cm0 = fmaxf(cm0, __shfl_xor_sync(0xffffffffu, cm0, 2));
            cm1 = fmaxf(cm1, __shfl_xor_sync(0xffffffffu, cm1, 1));
            cm1 = fmaxf(cm1, __shfl_xor_sync(0xffffffffu, cm1, 2));
            float mn0 = fmaxf(mr[0], cm0), mn1 = fmaxf(mr[1], cm1);
            float c0 = ex2f(mr[0] - mn0), c1 = ex2f(mr[1] - mn1);
            se[0] *= c0; st[0] *= c0;
            se[1] *= c1; st[1] *= c1;
#pragma unroll
            for (int nt = 0; nt < 8; nt++) {
                o[nt].x *= c0; o[nt].y *= c0;
                o[nt].z *= c1; o[nt].w *= c1;
            }
            mr[0] = mn0; mr[1] = mn1;
            // p, stats, PV
#pragma unroll
            for (int kk = 0; kk < 4; kk++) {
                u32 ah4[4];
#pragma unroll
                for (int half = 0; half < 2; half++) {
                    int nt = 2 * kk + half;
                    float p0 = ex2f(s[nt].x - mn0);
                    float p1 = ex2f(s[nt].y - mn0);
                    float p2 = ex2f(s[nt].z - mn1);
                    float p3 = ex2f(s[nt].w - mn1);
                    se[0] += p0 + p1; se[1] += p2 + p3;
                    st[0] = fmaf(p0, s[nt].x, st[0]); st[0] = fmaf(p1, s[nt].y, st[0]);
                    st[1] = fmaf(p2, s[nt].z, st[1]); st[1] = fmaf(p3, s[nt].w, st[1]);
                    ah4[half * 2 + 0] = packh(p0, p1);
                    ah4[half * 2 + 1] = packh(p2, p3);
                }
#pragma unroll
                for (int ntp = 0; ntp < 4; ntp++) {
                    u32 vh4[4], vl4[4];
                    ldmx4t(vh4, vb + (u32)(kk * 2304 + ntp * 32));
                    ldmx4t(vl4, vb + AKPL + (u32)(kk * 2304 + ntp * 32));
                    mma2h(o[ntp*2+0], ah4, vh4, vl4, 0);
                    mma2h(o[ntp*2+1], ah4, vh4, vl4, 1);
                }
            }
        }
    }

    // stats reductions + beta
    float bsc[2], bm[2], nrm[2];
#pragma unroll
    for (int rr = 0; rr < 2; rr++) {
        se[rr] += __shfl_xor_sync(0xffffffffu, se[rr], 1);
        se[rr] += __shfl_xor_sync(0xffffffffu, se[rr], 2);
        st[rr] += __shfl_xor_sync(0xffffffffu, st[rr], 1);
        st[rr] += __shfl_xor_sync(0xffffffffu, st[rr], 2);
        float ent = LN2 * (lg2f(se[rr]) + mr[rr] - st[rr] / se[rr]);
        float beta = 1.f;
        if (ent > 0.5f) {
            float poly = ((((-0.037f * ent + 0.481f) * ent - 2.3f) * ent + 4.917f) * ent - 1.791f);
            beta = fmaxf(poly, 1.f);
        }
        bsc[rr] = beta;
        bm[rr] = beta * mr[rr];
        nrm[rr] = se[rr];
    }
    bool wneed = !__all_sync(0xffffffffu, (bsc[0] == 1.f) && (bsc[1] == 1.f));
    if (lane == 0) sflags[wid] = wneed ? 1 : 0;
    __syncthreads();
    int ctaNeed = 0;
#pragma unroll
    for (int w = 0; w < 8; w++) ctaNeed |= sflags[w];

    // ===== pass B (rare): recompute QK with beta scaling =====
    if (ctaNeed) {
        float l2[2] = {0.f, 0.f};
        if (wneed) {
#pragma unroll
            for (int nt = 0; nt < 8; nt++) o[nt] = make_float4(0.f,0.f,0.f,0.f);
        }
        a_issueKV(sb + AK_OFF, Kh, Kl, Vh, Vl, 0, tid);
        cpa_commit();
        for (int kt = 0; kt <= ktmax; kt++) {
            int ktb = kt * 64;
            bool act = (ktb <= q0 + wr + 15);
            cpa_wait0();
            __syncthreads();
            if (kt < ktmax) {
                a_issueKV(sb + AK_OFF + (u32)((kt + 1) & 1) * ABF, Kh, Kl, Vh, Vl, ktb + 64, tid);
                cpa_commit();
            }
            if (act && wneed) {
                u32 kb = sb + AK_OFF + (u32)(kt & 1) * ABF + kOff;
                u32 vb = sb + AK_OFF + (u32)(kt & 1) * ABF + 2u * AKPL + vOff;
                float4 s[8];
                qk_tile(s, qBase, kb);
#pragma unroll
                for (int kk = 0; kk < 4; kk++) {
                    u32 ah4[4];
#pragma unroll
                    for (int half = 0; half < 2; half++) {
                        int nt = 2 * kk + half;
                        int gc = ktb + nt * 8 + 2 * t;
                        float a0 = (gc     <= gr0) ? s[nt].x * SCL : -1e30f;
                        float a1 = (gc + 1 <= gr0) ? s[nt].y * SCL : -1e30f;
                        float b0 = (gc     <= gr1) ? s[nt].z * SCL : -1e30f;
                        float b1 = (gc + 1 <= gr1) ? s[nt].w * SCL : -1e30f;
                        float p0 = ex2f(fmaf(bsc[0], a0, -bm[0]));
                        float p1 = ex2f(fmaf(bsc[0], a1, -bm[0]));
                        float p2 = ex2f(fmaf(bsc[1], b0, -bm[1]));
                        float p3 = ex2f(fmaf(bsc[1], b1, -bm[1]));
                        l2[0] += p0 + p1; l2[1] += p2 + p3;
                        ah4[half * 2 + 0] = packh(p0, p1);
                        ah4[half * 2 + 1] = packh(p2, p3);
                    }
#pragma unroll
                    for (int ntp = 0; ntp < 4; ntp++) {
                        u32 vh4[4], vl4[4];
                        ldmx4t(vh4, vb + (u32)(kk * 2304 + ntp * 32));
                        ldmx4t(vl4, vb + AKPL + (u32)(kk * 2304 + ntp * 32));
                        mma2h(o[ntp*2+0], ah4, vh4, vl4, 0);
                        mma2h(o[ntp*2+1], ah4, vh4, vl4, 1);
                    }
                }
            }
        }
        if (wneed) {
#pragma unroll
            for (int rr = 0; rr < 2; rr++) {
                l2[rr] += __shfl_xor_sync(0xffffffffu, l2[rr], 1);
                l2[rr] += __shfl_xor_sync(0xffffffffu, l2[rr], 2);
                nrm[rr] = l2[rr];
            }
        }
    }

    float inv0 = 1.f / nrm[0], inv1 = 1.f / nrm[1];
    size_t row0 = ((size_t)(b * NN) + gr0) * DD + h * HD;
    size_t row1 = ((size_t)(b * NN) + gr1) * DD + h * HD;
#pragma unroll
    for (int nt = 0; nt < 8; nt++) {
        int c = nt * 8 + 2 * t;
        u16 h0,l0h,h1,l1h;
        bsplit(o[nt].x * inv0, h0, l0h); bsplit(o[nt].y * inv0, h1, l1h);
        *(ushort2*)&g_cth[row0 + c] = make_ushort2(h0,h1);
        *(ushort2*)&g_ctl[row0 + c] = make_ushort2(l0h,l1h);
        bsplit(o[nt].z * inv1, h0, l0h); bsplit(o[nt].w * inv1, h1, l1h);
        *(ushort2*)&g_cth[row1 + c] = make_ushort2(h0,h1);
        *(ushort2*)&g_ctl[row1 + c] = make_ushort2(l0h,l1h);
    }
}

// ============================================================
extern "C" void kernel_launch(void* const* d_in, const int* in_sizes, int n_in,
                              void* d_out, int out_size)
{
    const float* x  = (const float*)d_in[0];
    const float* Wq = (const float*)d_in[1];
    const float* Wk = (const float*)d_in[2];
    const float* Wv = (const float*)d_in[3];
    const float* Wo = (const float*)d_in[4];
    const float* bo = (const float*)d_in[5];
    float* out = (float*)d_out;

    const int gsmem = 3 * (int)GSTG;
    cudaFuncSetAttribute(gemm_qkv, cudaFuncAttributeMaxDynamicSharedMemorySize, gsmem);
    cudaFuncSetAttribute(gemm_out, cudaFuncAttributeMaxDynamicSharedMemorySize, gsmem);
    cudaFuncSetAttribute(attn_mma, cudaFuncAttributeMaxDynamicSharedMemorySize, ASMEM);

    presplitAll<<<8192, 256>>>((const float4*)x, (const float4*)Wq, (const float4*)Wk,
                               (const float4*)Wv, (const float4*)Wo);

    gemm_qkv<<<296, 256, gsmem>>>();

    attn_mma<<<512, 256, ASMEM>>>();

    dim3 og(8, 32);
    gemm_out<<<og, 256, gsmem>>>(bo, out);
}

// round 15
// speedup vs baseline: 1.0945x; 1.0945x over previous
#include <cuda_runtime.h>
#include <cstdint>

#define BB 2
#define NN 2048
#define DD 1024
#define HH 16
#define HD 64
typedef unsigned short u16;
typedef uint32_t u32;

__device__ __align__(16) u16 g_xh[(size_t)BB*NN*DD];
__device__ __align__(16) u16 g_xl[(size_t)BB*NN*DD];
__device__ __align__(16) u16 g_wh[4][(size_t)DD*DD];
__device__ __align__(16) u16 g_wl[4][(size_t)DD*DD];
__device__ __align__(16) u16 g_qh[(size_t)BB*HH*NN*HD];   // fp16 (single plane)
__device__ __align__(16) u16 g_kh[(size_t)BB*HH*NN*HD];   // fp16 hi
__device__ __align__(16) u16 g_kl[(size_t)BB*HH*NN*HD];   // fp16 lo
__device__ __align__(16) u16 g_vh[(size_t)BB*HH*NN*HD];   // fp16 hi
__device__ __align__(16) u16 g_vl[(size_t)BB*HH*NN*HD];   // fp16 lo
__device__ __align__(16) u16 g_cth[(size_t)BB*NN*DD];
__device__ __align__(16) u16 g_ctl[(size_t)BB*NN*DD];
__device__ float g_s[(size_t)512*262144];

__device__ __forceinline__ void bsplit(float x, u16 &h, u16 &l){
    asm("cvt.rn.bf16.f32 %0, %1;" : "=h"(h) : "f"(x));
    float hf = __uint_as_float((u32)h << 16);
    asm("cvt.rn.bf16.f32 %0, %1;" : "=h"(l) : "f"(x - hf));
}
__device__ __forceinline__ void hsplit(float x, u16 &h, u16 &l){
    asm("cvt.rn.f16.f32 %0, %1;" : "=h"(h) : "f"(x));
    float hf; asm("cvt.f32.f16 %0, %1;" : "=f"(hf) : "h"(h));
    asm("cvt.rn.f16.f32 %0, %1;" : "=h"(l) : "f"(x - hf));
}
__device__ __forceinline__ u16 h1(float x){
    u16 h; asm("cvt.rn.f16.f32 %0, %1;" : "=h"(h) : "f"(x));
    return h;
}
__device__ __forceinline__ u32 packh(float lo, float hi){
    u32 r; asm("cvt.rn.f16x2.f32 %0, %1, %2;" : "=r"(r) : "f"(hi), "f"(lo));
    return r;
}
__device__ __forceinline__ float ex2f(float x){
    float r; asm("ex2.approx.ftz.f32 %0, %1;" : "=f"(r) : "f"(x));
    return r;
}
__device__ __forceinline__ float lg2f(float x){
    float r; asm("lg2.approx.ftz.f32 %0, %1;" : "=f"(r) : "f"(x));
    return r;
}
__device__ __forceinline__ u32 smem_u32(const void* p){
    u32 a;
    asm("{ .reg .u64 t; cvta.to.shared.u64 t, %1; cvt.u32.u64 %0, t; }" : "=r"(a) : "l"(p));
    return a;
}
__device__ __forceinline__ void cpa16(u32 dst, const void* src){
    asm volatile("cp.async.cg.shared.global [%0], [%1], 16;" :: "r"(dst), "l"(src));
}
__device__ __forceinline__ void cpa_commit(){ asm volatile("cp.async.commit_group;" ::: "memory"); }
__device__ __forceinline__ void cpa_wait0(){ asm volatile("cp.async.wait_group 0;" ::: "memory"); }
__device__ __forceinline__ void cpa_wait1(){ asm volatile("cp.async.wait_group 1;" ::: "memory"); }

__device__ __forceinline__ void ldmx4(u32* r, u32 a){
    asm volatile("ldmatrix.sync.aligned.m8n8.x4.shared.b16 {%0,%1,%2,%3}, [%4];"
        : "=r"(r[0]), "=r"(r[1]), "=r"(r[2]), "=r"(r[3]) : "r"(a));
}
__device__ __forceinline__ void ldmx4t(u32* r, u32 a){
    asm volatile("ldmatrix.sync.aligned.m8n8.x4.trans.shared.b16 {%0,%1,%2,%3}, [%4];"
        : "=r"(r[0]), "=r"(r[1]), "=r"(r[2]), "=r"(r[3]) : "r"(a));
}
__device__ __forceinline__ void mmab(float4& d, const u32* a, u32 b0, u32 b1){
    asm volatile("mma.sync.aligned.m16n8k16.row.col.f32.bf16.bf16.f32 "
        "{%0,%1,%2,%3},{%4,%5,%6,%7},{%8,%9},{%0,%1,%2,%3};"
        : "+f"(d.x), "+f"(d.y), "+f"(d.z), "+f"(d.w)
        : "r"(a[0]), "r"(a[1]), "r"(a[2]), "r"(a[3]), "r"(b0), "r"(b1));
}
__device__ __forceinline__ void mmah(float4& d, const u32* a, u32 b0, u32 b1){
    asm volatile("mma.sync.aligned.m16n8k16.row.col.f32.f16.f16.f32 "
        "{%0,%1,%2,%3},{%4,%5,%6,%7},{%8,%9},{%0,%1,%2,%3};"
        : "+f"(d.x), "+f"(d.y), "+f"(d.z), "+f"(d.w)
        : "r"(a[0]), "r"(a[1]), "r"(a[2]), "r"(a[3]), "r"(b0), "r"(b1));
}
__device__ __forceinline__ void mma3b(float4& d, const u32* ah, const u32* al,
                                      const u32* bh, const u32* bl, int ng){
    mmab(d, ah, bh[2*ng], bh[2*ng+1]);
    mmab(d, ah, bl[2*ng], bl[2*ng+1]);
    mmab(d, al, bh[2*ng], bh[2*ng+1]);
}
__device__ __forceinline__ void mma2h(float4& d, const u32* ah,
                                      const u32* bh, const u32* bl, int ng){
    mmah(d, ah, bh[2*ng], bh[2*ng+1]);
    mmah(d, ah, bl[2*ng], bl[2*ng+1]);
}

// ============================================================
// presplit (single launch; x + W in bf16 hi/lo)
// ============================================================
__device__ __forceinline__ void dosplit4(const float4* src, ushort4* hi, ushort4* lo, int i){
    float4 v = src[i];
    u16 h0,l0,h1_,l1,h2,l2,h3,l3;
    bsplit(v.x,h0,l0); bsplit(v.y,h1_,l1); bsplit(v.z,h2,l2); bsplit(v.w,h3,l3);
    hi[i] = make_ushort4(h0,h1_,h2,h3);
    lo[i] = make_ushort4(l0,l1,l2,l3);
}
__global__ __launch_bounds__(256) void presplitAll(const float4* __restrict__ x,
                                                   const float4* __restrict__ Wq,
                                                   const float4* __restrict__ Wk,
                                                   const float4* __restrict__ Wv,
                                                   const float4* __restrict__ Wo){
    int bid = blockIdx.x;
    if (bid < 4096) {
        dosplit4(x, (ushort4*)g_xh, (ushort4*)g_xl, bid * 256 + threadIdx.x);
    } else {
        int m = (bid - 4096) >> 10;
        int i = ((bid - 4096) & 1023) * 256 + threadIdx.x;
        const float4* src = (m == 0) ? Wq : (m == 1) ? Wk : (m == 2) ? Wv : Wo;
        dosplit4(src, (ushort4*)g_wh[m], (ushort4*)g_wl[m], i);
    }
}

// ============================================================
// GEMM core: 128x128 tile, BK=32, SW64-swizzled rows, 3-stage.
// ============================================================
#define GPL 8192u
#define GSTG 32768u

__device__ __forceinline__ void g_issue(u32 st,
        const u16* __restrict__ Ah, const u16* __restrict__ Al,
        const u16* __restrict__ Bh, const u16* __restrict__ Bl,
        int m0, int n0, int k0, int tid){
#pragma unroll
    for (int i = 0; i < 8; i++) {
        int idx = tid + i * 256;
        int p = idx >> 9, q = idx & 511;
        int r = q >> 2, c = q & 3;
        u32 sa = st + (u32)p * GPL + (u32)(r * 64 + ((c * 16) ^ (((r >> 1) & 3) << 4)));
        const u16* g = (p == 0) ? Ah : (p == 1) ? Al : (p == 2) ? Bh : Bl;
        int rb = (p < 2) ? m0 : n0;
        cpa16(sa, g + (size_t)(rb + r) * DD + k0 + c * 8);
    }
}

__device__ __forceinline__ void g_run(const u16* Ah, const u16* Al, const u16* Bh, const u16* Bl,
                                      char* sm, int m0, int n0, int tid,
                                      float4 (&acc)[2][8], int wm, int wn, int lane){
    u32 sb = smem_u32(sm);
    const int arow = wm * 32 + (lane & 7) + 8 * ((lane >> 3) & 1);
    const int brow = wn * 64 + (lane & 7) + 8 * ((lane >> 4) & 1);
    const u32 axm = ((((lane & 7) >> 1) & 3) << 4);
    const u32 bxm = axm;
    const u32 aB = sb + (u32)(arow * 64);
    const u32 bB = sb + 2u * GPL + (u32)(brow * 64);
    const u32 a16 = 16u * (u32)(lane >> 4);
    const u32 b16 = 16u * (u32)((lane >> 3) & 1);

    g_issue(sb,        Ah, Al, Bh, Bl, m0, n0, 0,  tid); cpa_commit();
    g_issue(sb + GSTG, Ah, Al, Bh, Bl, m0, n0, 32, tid); cpa_commit();
    for (int it = 0; it < 32; it++) {
        u32 so = (u32)(it % 3) * GSTG;
        if (it < 31) cpa_wait1(); else cpa_wait0();
        __syncthreads();
        if (it + 2 < 32) {
            g_issue(sb + (u32)((it + 2) % 3) * GSTG, Ah, Al, Bh, Bl, m0, n0, (it + 2) * 32, tid);
            cpa_commit();
        }
#pragma unroll
        for (int kk = 0; kk < 2; kk++) {
            u32 ah4[2][4], al4[2][4];
            u32 ao = ((u32)(kk * 32) + a16) ^ axm;
#pragma unroll
            for (int mt = 0; mt < 2; mt++) {
                ldmx4(ah4[mt], aB + so + (u32)(mt * 1024) + ao);
                ldmx4(al4[mt], aB + so + GPL + (u32)(mt * 1024) + ao);
            }
            u32 bo = ((u32)(kk * 32) + b16) ^ bxm;
#pragma unroll
            for (int ntp = 0; ntp < 4; ntp++) {
                u32 bh4[4], bl4[4];
                ldmx4(bh4, bB + so + (u32)(ntp * 1024) + bo);
                ldmx4(bl4, bB + so + GPL + (u32)(ntp * 1024) + bo);
#pragma unroll
                for (int mt = 0; mt < 2; mt++) {
                    mma3b(acc[mt][ntp*2+0], ah4[mt], al4[mt], bh4, bl4, 0);
                    mma3b(acc[mt][ntp*2+1], ah4[mt], al4[mt], bh4, bl4, 1);
                }
            }
        }
    }
}

// persistent QKV: grid = 296, stride loop over 768 tiles
__global__ __launch_bounds__(256, 2) void gemm_qkv(void)
{
    extern __shared__ char gsm[];
    const int tid = threadIdx.x, lane = tid & 31, wid = tid >> 5;
    const int g = lane >> 2, t = lane & 3;
    const int wm = wid >> 1, wn = wid & 1;

    for (int tile = blockIdx.x; tile < 768; tile += gridDim.x) {
        const int mat = tile >> 8, rem = tile & 255;
        const int m0 = (rem >> 3) * 128, n0 = (rem & 7) * 128;
        const u16 *Bh = g_wh[mat], *Bl = g_wl[mat];

        float4 acc[2][8];
#pragma unroll
        for (int i = 0; i < 2; i++)
#pragma unroll
            for (int j = 0; j < 8; j++) acc[i][j] = make_float4(0.f,0.f,0.f,0.f);

        __syncthreads();
        g_run(g_xh, g_xl, Bh, Bl, gsm, m0, n0, tid, acc, wm, wn, lane);

#pragma unroll
        for (int mt = 0; mt < 2; mt++) {
            int r0 = m0 + wm * 32 + mt * 16 + g;
#pragma unroll
            for (int nt = 0; nt < 8; nt++) {
                int n = n0 + wn * 64 + nt * 8 + 2 * t;
                int h = n >> 6, cc = n & 63;
                float4 c = acc[mt][nt];
                int b0r = r0 >> 11, i0r = r0 & (NN - 1);
                int b1r = (r0 + 8) >> 11, i1r = (r0 + 8) & (NN - 1);
                size_t i0 = ((size_t)(b0r * HH + h) * NN + i0r) * HD + cc;
                size_t i1 = ((size_t)(b1r * HH + h) * NN + i1r) * HD + cc;
                if (mat == 0) {
                    *(ushort2*)&g_qh[i0] = make_ushort2(h1(c.x), h1(c.y));
                    *(ushort2*)&g_qh[i1] = make_ushort2(h1(c.z), h1(c.w));
                } else {
                    u16 *Ch = (mat == 1) ? g_kh : g_vh;
                    u16 *Cl = (mat == 1) ? g_kl : g_vl;
                    u16 h0,l0,hh1,l1;
                    hsplit(c.x,h0,l0); hsplit(c.y,hh1,l1);
                    *(ushort2*)&Ch[i0] = make_ushort2(h0,hh1);
                    *(ushort2*)&Cl[i0] = make_ushort2(l0,l1);
                    hsplit(c.z,h0,l0); hsplit(c.w,hh1,l1);
                    *(ushort2*)&Ch[i1] = make_ushort2(h0,hh1);
                    *(ushort2*)&Cl[i1] = make_ushort2(l0,l1);
                }
            }
        }
    }
}

__global__ __launch_bounds__(256, 2) void gemm_out(const float* __restrict__ bias,
                                                   float* __restrict__ C)
{
    extern __shared__ char gsm[];
    const int tid = threadIdx.x, lane = tid & 31, wid = tid >> 5;
    const int g = lane >> 2, t = lane & 3;
    const int wm = wid >> 1, wn = wid & 1;
    const int m0 = blockIdx.y * 128, n0 = blockIdx.x * 128;

    float4 acc[2][8];
#pragma unroll
    for (int i = 0; i < 2; i++)
#pragma unroll
        for (int j = 0; j < 8; j++) acc[i][j] = make_float4(0.f,0.f,0.f,0.f);

    g_run(g_cth, g_ctl, g_wh[3], g_wl[3], gsm, m0, n0, tid, acc, wm, wn, lane);

#pragma unroll
    for (int mt = 0; mt < 2; mt++) {
        int r0 = m0 + wm * 32 + mt * 16 + g;
#pragma unroll
        for (int nt = 0; nt < 8; nt++) {
            int n = n0 + wn * 64 + nt * 8 + 2 * t;
            float bx = bias[n], by = bias[n + 1];
            float4 c = acc[mt][nt];
            *(float2*)&C[(size_t)r0 * DD + n]       = make_float2(c.x + bx, c.y + by);
            *(float2*)&C[(size_t)(r0 + 8) * DD + n] = make_float2(c.z + bx, c.w + by);
        }
    }
}

// ============================================================
// Attention (R13 base): S cached (log2), fixed-ref stats.
// QK = 2-term fp16 (Q single plane, K hi+lo). PV = fp16 2-term.
// ============================================================
#define ARS 144
#define AQPL 18432u    // Q single plane
#define AKPL 9216u
#define AK_OFF 18432u
#define ABUF 18432u
#define ASMEM 55296
#define SCL 0.180336880f
#define LN2 0.693147181f
#define M0F 32.0f

__device__ __forceinline__ void a_issueKV(u32 bufBase, const u16* __restrict__ gh,
                                          const u16* __restrict__ gl, int row0, int tid){
#pragma unroll
    for (int i = 0; i < 4; i++) {
        int p = i >> 1;
        int rem = tid + (i & 1) * 256;
        int r = rem >> 3, c = rem & 7;
        u32 sa = bufBase + (u32)p * AKPL + (u32)(r * ARS + c * 16);
        const u16* g = p ? gl : gh;
        cpa16(sa, g + (size_t)(row0 + r) * HD + c * 8);
    }
}

__global__ __launch_bounds__(256, 2) void attn_mma(void)
{
    extern __shared__ char sm[];
    u32 sb = smem_u32(sm);

    const int tid = threadIdx.x, lane = tid & 31, wid = tid >> 5;
    const int g = lane >> 2, t = lane & 3;
    const int qt = 15 - (int)(blockIdx.x >> 5);
    const int bh = blockIdx.x & 31;
    const int h = bh >> 1, b = bh & 1;
    const int q0 = qt * 128, ktmax = 2 * qt + 1;
    const size_t ho = (size_t)(b * HH + h) * NN * HD;
    const u16 *Qh = g_qh + ho;
    const u16 *Kh = g_kh + ho, *Kl = g_kl + ho;
    const u16 *Vh = g_vh + ho, *Vl = g_vl + ho;
    float* Sc = g_s + (size_t)((b * HH + h) * 16 + qt) * 262144 + wid * 1024 + lane * 2;

    const int wr = wid * 16;
    const int gr0 = q0 + wr + g, gr1 = gr0 + 8;

    const u32 qBase = sb + (u32)((wr + (lane & 7) + 8 * ((lane >> 3) & 1)) * ARS + 16 * (lane >> 4));
    const u32 kOff = (u32)(((lane & 7) + 8 * ((lane >> 4) & 1)) * ARS + 16 * ((lane >> 3) & 1));
    const u32 vOff = (u32)(((lane & 7) + 8 * ((lane >> 3) & 1)) * ARS + 16 * (lane >> 4));

    // Q tile: single fp16 plane (1024 chunks)
#pragma unroll
    for (int i = 0; i < 4; i++) {
        int rem = tid + i * 256;
        int r = rem >> 3, c = rem & 7;
        cpa16(sb + (u32)(r * ARS + c * 16), Qh + (size_t)(q0 + r) * HD + c * 8);
    }
    a_issueKV(sb + AK_OFF, Kh, Kl, 0, tid);
    cpa_commit();

    float mx[2] = {-1e30f, -1e30f}, se[2] = {0.f, 0.f}, st2[2] = {0.f, 0.f};

    // ===== pass A: 2-term fp16 QK, fixed-ref stats, store S =====
    for (int kt = 0; kt <= ktmax; kt++) {
        int ktb = kt * 64;
        bool act = (ktb <= q0 + wr + 15);
        cpa_wait0();
        __syncthreads();
        if (kt < ktmax) {
            a_issueKV(sb + AK_OFF + (u32)((kt + 1) & 1) * ABUF, Kh, Kl, ktb + 64, tid);
            cpa_commit();
        }
        if (act) {
            u32 kb = sb + AK_OFF + (u32)(kt & 1) * ABUF + kOff;
            float4 s[8];
#pragma unroll
            for (int nt = 0; nt < 8; nt++) s[nt] = make_float4(0.f,0.f,0.f,0.f);
#pragma unroll
            for (int kk = 0; kk < 4; kk++) {
                u32 qh4[4];
                ldmx4(qh4, qBase + (u32)(kk * 32));
#pragma unroll
                for (int ntp = 0; ntp < 4; ntp++) {
                    u32 bh4[4], bl4[4];
                    ldmx4(bh4, kb + (u32)(ntp * 2304 + kk * 32));
                    ldmx4(bl4, kb + AKPL + (u32)(ntp * 2304 + kk * 32));
                    mma2h(s[ntp*2+0], qh4, bh4, bl4, 0);
                    mma2h(s[ntp*2+1], qh4, bh4, bl4, 1);
                }
            }
            float* sp = Sc + kt * 8192;
#pragma unroll
            for (int rr = 0; rr < 2; rr++) {
                int gr = rr ? gr1 : gr0;
#pragma unroll
                for (int nt = 0; nt < 8; nt++) {
                    float x0 = rr ? s[nt].z : s[nt].x;
                    float x1 = rr ? s[nt].w : s[nt].y;
                    int gc = ktb + nt * 8 + 2 * t;
                    float sv0 = (gc     <= gr) ? x0 * SCL : -1e30f;
                    float sv1 = (gc + 1 <= gr) ? x1 * SCL : -1e30f;
                    mx[rr] = fmaxf(mx[rr], fmaxf(sv0, sv1));
                    *(float2*)&sp[(rr * 8 + nt) * 64] = make_float2(sv0, sv1);
                    float e0 = ex2f(sv0 - M0F);
                    float e1 = ex2f(sv1 - M0F);
                    se[rr] += e0 + e1;
                    st2[rr] = fmaf(e0, sv0, st2[rr]);
                    st2[rr] = fmaf(e1, sv1, st2[rr]);
                }
            }
        }
    }

    float bsc[2], bm[2], l2[2] = {0.f, 0.f};
#pragma unroll
    for (int rr = 0; rr < 2; rr++) {
        mx[rr] = fmaxf(mx[rr], __shfl_xor_sync(0xffffffffu, mx[rr], 1));
        mx[rr] = fmaxf(mx[rr], __shfl_xor_sync(0xffffffffu, mx[rr], 2));
        se[rr] += __shfl_xor_sync(0xffffffffu, se[rr], 1);
        se[rr] += __shfl_xor_sync(0xffffffffu, se[rr], 2);
        st2[rr] += __shfl_xor_sync(0xffffffffu, st2[rr], 1);
        st2[rr] += __shfl_xor_sync(0xffffffffu, st2[rr], 2);
        float ent = LN2 * (lg2f(se[rr]) + M0F - st2[rr] / se[rr]);
        float beta = 1.f;
        if (ent > 0.5f) {
            float poly = ((((-0.037f * ent + 0.481f) * ent - 2.3f) * ent + 4.917f) * ent - 1.791f);
            beta = fmaxf(poly, 1.f);
        }
        bsc[rr] = beta;
        bm[rr] = beta * mx[rr];
    }

    float4 o[8];
#pragma unroll
    for (int nt = 0; nt < 8; nt++) o[nt] = make_float4(0.f,0.f,0.f,0.f);

    __syncthreads();
    a_issueKV(sb + AK_OFF, Vh, Vl, 0, tid);
    cpa_commit();

    // ===== pass B: P (fp16) from cached S, O += P * (Vh+Vl) =====
    for (int kt = 0; kt <= ktmax; kt++) {
        int ktb = kt * 64;
        bool act = (ktb <= q0 + wr + 15);
        cpa_wait0();
        __syncthreads();
        if (kt < ktmax) {
            a_issueKV(sb + AK_OFF + (u32)((kt + 1) & 1) * ABUF, Vh, Vl, ktb + 64, tid);
            cpa_commit();
        }
        if (act) {
            u32 vb = sb + AK_OFF + (u32)(kt & 1) * ABUF + vOff;
            const float* sp = Sc + kt * 8192;
#pragma unroll
            for (int kk = 0; kk < 4; kk++) {
                u32 ah4[4];
#pragma unroll
                for (int half = 0; half < 2; half++) {
                    int nt = 2 * kk + half;
#pragma unroll
                    for (int rr = 0; rr < 2; rr++) {
                        float2 sv2 = *(const float2*)&sp[(rr * 8 + nt) * 64];
                        float p0 = ex2f(fmaf(bsc[rr], sv2.x, -bm[rr]));
                        float p1 = ex2f(fmaf(bsc[rr], sv2.y, -bm[rr]));
                        l2[rr] += p0 + p1;
                        ah4[half * 2 + rr] = packh(p0, p1);
                    }
                }
#pragma unroll
                for (int ntp = 0; ntp < 4; ntp++) {
                    u32 vh4[4], vl4[4];
                    ldmx4t(vh4, vb + (u32)(kk * 2304 + ntp * 32));
                    ldmx4t(vl4, vb + AKPL + (u32)(kk * 2304 + ntp * 32));
                    mma2h(o[ntp*2+0], ah4, vh4, vl4, 0);
                    mma2h(o[ntp*2+1], ah4, vh4, vl4, 1);
                }
            }
        }
    }

#pragma unroll
    for (int rr = 0; rr < 2; rr++) {
        l2[rr] += __shfl_xor_sync(0xffffffffu, l2[rr], 1);
        l2[rr] += __shfl_xor_sync(0xffffffffu, l2[rr], 2);
    }
    float inv0 = 1.f / l2[0], inv1 = 1.f / l2[1];
    size_t row0 = ((size_t)(b * NN) + gr0) * DD + h * HD;
    size_t row1 = ((size_t)(b * NN) + gr1) * DD + h * HD;
#pragma unroll
    for (int nt = 0; nt < 8; nt++) {
        int c = nt * 8 + 2 * t;
        u16 h0,l0h,hh1,l1h;
        bsplit(o[nt].x * inv0, h0, l0h); bsplit(o[nt].y * inv0, hh1, l1h);
        *(ushort2*)&g_cth[row0 + c] = make_ushort2(h0,hh1);
        *(ushort2*)&g_ctl[row0 + c] = make_ushort2(l0h,l1h);
        bsplit(o[nt].z * inv1, h0, l0h); bsplit(o[nt].w * inv1, hh1, l1h);
        *(ushort2*)&g_cth[row1 + c] = make_ushort2(h0,hh1);
        *(ushort2*)&g_ctl[row1 + c] = make_ushort2(l0h,l1h);
    }
}

// ============================================================
extern "C" void kernel_launch(void* const* d_in, const int* in_sizes, int n_in,
                              void* d_out, int out_size)
{
    const float* x  = (const float*)d_in[0];
    const float* Wq = (const float*)d_in[1];
    const float* Wk = (const float*)d_in[2];
    const float* Wv = (const float*)d_in[3];
    const float* Wo = (const float*)d_in[4];
    const float* bo = (const float*)d_in[5];
    float* out = (float*)d_out;

    const int gsmem = 3 * (int)GSTG;
    cudaFuncSetAttribute(gemm_qkv, cudaFuncAttributeMaxDynamicSharedMemorySize, gsmem);
    cudaFuncSetAttribute(gemm_out, cudaFuncAttributeMaxDynamicSharedMemorySize, gsmem);
    cudaFuncSetAttribute(attn_mma, cudaFuncAttributeMaxDynamicSharedMemorySize, ASMEM);

    presplitAll<<<8192, 256>>>((const float4*)x, (const float4*)Wq, (const float4*)Wk,
                               (const float4*)Wv, (const float4*)Wo);

    gemm_qkv<<<296, 256, gsmem>>>();

    attn_mma<<<512, 256, ASMEM>>>();

    dim3 og(8, 32);
    gemm_out<<<og, 256, gsmem>>>(bo, out);
}

// round 16
// speedup vs baseline: 1.3774x; 1.2585x over previous
#include <cuda_runtime.h>
#include <cstdint>

#define BB 2
#define NN 2048
#define DD 1024
#define HH 16
#define HD 64
typedef unsigned short u16;
typedef uint32_t u32;

__device__ __align__(16) u16 g_xh[(size_t)BB*NN*DD];          // fp16 single plane
__device__ __align__(16) u16 g_wh[4][(size_t)DD*DD];          // fp16 hi
__device__ __align__(16) u16 g_wl[4][(size_t)DD*DD];          // fp16 lo
__device__ __align__(16) u16 g_qh[(size_t)BB*HH*NN*HD];       // fp16 single plane
__device__ __align__(16) u16 g_kh[(size_t)BB*HH*NN*HD];
__device__ __align__(16) u16 g_kl[(size_t)BB*HH*NN*HD];
__device__ __align__(16) u16 g_vh[(size_t)BB*HH*NN*HD];
__device__ __align__(16) u16 g_vl[(size_t)BB*HH*NN*HD];
__device__ __align__(16) u16 g_cth[(size_t)BB*NN*DD];         // ctx fp16 single plane
__device__ float g_s[(size_t)512*262144];

__device__ __forceinline__ void hsplit(float x, u16 &h, u16 &l){
    asm("cvt.rn.f16.f32 %0, %1;" : "=h"(h) : "f"(x));
    float hf; asm("cvt.f32.f16 %0, %1;" : "=f"(hf) : "h"(h));
    asm("cvt.rn.f16.f32 %0, %1;" : "=h"(l) : "f"(x - hf));
}
__device__ __forceinline__ u16 h1(float x){
    u16 h; asm("cvt.rn.f16.f32 %0, %1;" : "=h"(h) : "f"(x));
    return h;
}
__device__ __forceinline__ u32 packh(float lo, float hi){
    u32 r; asm("cvt.rn.f16x2.f32 %0, %1, %2;" : "=r"(r) : "f"(hi), "f"(lo));
    return r;
}
__device__ __forceinline__ float ex2f(float x){
    float r; asm("ex2.approx.ftz.f32 %0, %1;" : "=f"(r) : "f"(x));
    return r;
}
__device__ __forceinline__ float lg2f(float x){
    float r; asm("lg2.approx.ftz.f32 %0, %1;" : "=f"(r) : "f"(x));
    return r;
}
__device__ __forceinline__ u32 smem_u32(const void* p){
    u32 a;
    asm("{ .reg .u64 t; cvta.to.shared.u64 t, %1; cvt.u32.u64 %0, t; }" : "=r"(a) : "l"(p));
    return a;
}
__device__ __forceinline__ void cpa16(u32 dst, const void* src){
    asm volatile("cp.async.cg.shared.global [%0], [%1], 16;" :: "r"(dst), "l"(src));
}
__device__ __forceinline__ void cpa_commit(){ asm volatile("cp.async.commit_group;" ::: "memory"); }
__device__ __forceinline__ void cpa_wait0(){ asm volatile("cp.async.wait_group 0;" ::: "memory"); }
__device__ __forceinline__ void cpa_wait1(){ asm volatile("cp.async.wait_group 1;" ::: "memory"); }

__device__ __forceinline__ void ldmx4(u32* r, u32 a){
    asm volatile("ldmatrix.sync.aligned.m8n8.x4.shared.b16 {%0,%1,%2,%3}, [%4];"
        : "=r"(r[0]), "=r"(r[1]), "=r"(r[2]), "=r"(r[3]) : "r"(a));
}
__device__ __forceinline__ void ldmx4t(u32* r, u32 a){
    asm volatile("ldmatrix.sync.aligned.m8n8.x4.trans.shared.b16 {%0,%1,%2,%3}, [%4];"
        : "=r"(r[0]), "=r"(r[1]), "=r"(r[2]), "=r"(r[3]) : "r"(a));
}
__device__ __forceinline__ void mmah(float4& d, const u32* a, u32 b0, u32 b1){
    asm volatile("mma.sync.aligned.m16n8k16.row.col.f32.f16.f16.f32 "
        "{%0,%1,%2,%3},{%4,%5,%6,%7},{%8,%9},{%0,%1,%2,%3};"
        : "+f"(d.x), "+f"(d.y), "+f"(d.z), "+f"(d.w)
        : "r"(a[0]), "r"(a[1]), "r"(a[2]), "r"(a[3]), "r"(b0), "r"(b1));
}
__device__ __forceinline__ void mma2h(float4& d, const u32* ah,
                                      const u32* bh, const u32* bl, int ng){
    mmah(d, ah, bh[2*ng], bh[2*ng+1]);
    mmah(d, ah, bl[2*ng], bl[2*ng+1]);
}

// ============================================================
// presplit: x,ctx-style fp16 single; W fp16 hi/lo. Single launch.
// ============================================================
__global__ __launch_bounds__(256) void presplitAll(const float4* __restrict__ x,
                                                   const float4* __restrict__ Wq,
                                                   const float4* __restrict__ Wk,
                                                   const float4* __restrict__ Wv,
                                                   const float4* __restrict__ Wo){
    int bid = blockIdx.x;
    if (bid < 4096) {
        int i = bid * 256 + threadIdx.x;
        float4 v = x[i];
        ((ushort4*)g_xh)[i] = make_ushort4(h1(v.x), h1(v.y), h1(v.z), h1(v.w));
    } else {
        int m = (bid - 4096) >> 10;
        int i = ((bid - 4096) & 1023) * 256 + threadIdx.x;
        const float4* src = (m == 0) ? Wq : (m == 1) ? Wk : (m == 2) ? Wv : Wo;
        float4 v = src[i];
        u16 h0,l0,hh1,l1,h2,l2,h3,l3;
        hsplit(v.x,h0,l0); hsplit(v.y,hh1,l1); hsplit(v.z,h2,l2); hsplit(v.w,h3,l3);
        ((ushort4*)g_wh[m])[i] = make_ushort4(h0,hh1,h2,h3);
        ((ushort4*)g_wl[m])[i] = make_ushort4(l0,l1,l2,l3);
    }
}

// ============================================================
// GEMM: 128x128 tile, BK=32, fp16 2-term (A single, B hi+lo).
// SW64-swizzled rows, 3-stage cp.async. Planes: A@0, Bh@8K, Bl@16K.
// ============================================================
#define GPL 8192u
#define GSTG 24576u

__device__ __forceinline__ void g_issue(u32 st,
        const u16* __restrict__ Ah,
        const u16* __restrict__ Bh, const u16* __restrict__ Bl,
        int m0, int n0, int k0, int tid){
#pragma unroll
    for (int i = 0; i < 6; i++) {
        int idx = tid + i * 256;
        int p = idx >> 9, q = idx & 511;
        int r = q >> 2, c = q & 3;
        u32 sa = st + (u32)p * GPL + (u32)(r * 64 + ((c * 16) ^ (((r >> 1) & 3) << 4)));
        const u16* g = (p == 0) ? Ah : (p == 1) ? Bh : Bl;
        int rb = (p == 0) ? m0 : n0;
        cpa16(sa, g + (size_t)(rb + r) * DD + k0 + c * 8);
    }
}

__device__ __forceinline__ void g_run(const u16* Ah, const u16* Bh, const u16* Bl,
                                      char* sm, int m0, int n0, int tid,
                                      float4 (&acc)[2][8], int wm, int wn, int lane){
    u32 sb = smem_u32(sm);
    const int arow = wm * 32 + (lane & 7) + 8 * ((lane >> 3) & 1);
    const int brow = wn * 64 + (lane & 7) + 8 * ((lane >> 4) & 1);
    const u32 axm = ((((lane & 7) >> 1) & 3) << 4);
    const u32 aB = sb + (u32)(arow * 64);
    const u32 bB = sb + GPL + (u32)(brow * 64);
    const u32 a16 = 16u * (u32)(lane >> 4);
    const u32 b16 = 16u * (u32)((lane >> 3) & 1);

    g_issue(sb,        Ah, Bh, Bl, m0, n0, 0,  tid); cpa_commit();
    g_issue(sb + GSTG, Ah, Bh, Bl, m0, n0, 32, tid); cpa_commit();
    for (int it = 0; it < 32; it++) {
        u32 so = (u32)(it % 3) * GSTG;
        if (it < 31) cpa_wait1(); else cpa_wait0();
        __syncthreads();
        if (it + 2 < 32) {
            g_issue(sb + (u32)((it + 2) % 3) * GSTG, Ah, Bh, Bl, m0, n0, (it + 2) * 32, tid);
            cpa_commit();
        }
#pragma unroll
        for (int kk = 0; kk < 2; kk++) {
            u32 ah4[2][4];
            u32 ao = ((u32)(kk * 32) + a16) ^ axm;
#pragma unroll
            for (int mt = 0; mt < 2; mt++)
                ldmx4(ah4[mt], aB + so + (u32)(mt * 1024) + ao);
            u32 bo = ((u32)(kk * 32) + b16) ^ axm;
#pragma unroll
            for (int ntp = 0; ntp < 4; ntp++) {
                u32 bh4[4], bl4[4];
                ldmx4(bh4, bB + so + (u32)(ntp * 1024) + bo);
                ldmx4(bl4, bB + so + GPL + (u32)(ntp * 1024) + bo);
#pragma unroll
                for (int mt = 0; mt < 2; mt++) {
                    mma2h(acc[mt][ntp*2+0], ah4[mt], bh4, bl4, 0);
                    mma2h(acc[mt][ntp*2+1], ah4[mt], bh4, bl4, 1);
                }
            }
        }
    }
}

// persistent QKV: grid = 296, stride loop over 768 tiles
__global__ __launch_bounds__(256, 2) void gemm_qkv(void)
{
    extern __shared__ char gsm[];
    const int tid = threadIdx.x, lane = tid & 31, wid = tid >> 5;
    const int g = lane >> 2, t = lane & 3;
    const int wm = wid >> 1, wn = wid & 1;

    for (int tile = blockIdx.x; tile < 768; tile += gridDim.x) {
        const int mat = tile >> 8, rem = tile & 255;
        const int m0 = (rem >> 3) * 128, n0 = (rem & 7) * 128;

        float4 acc[2][8];
#pragma unroll
        for (int i = 0; i < 2; i++)
#pragma unroll
            for (int j = 0; j < 8; j++) acc[i][j] = make_float4(0.f,0.f,0.f,0.f);

        __syncthreads();
        g_run(g_xh, g_wh[mat], g_wl[mat], gsm, m0, n0, tid, acc, wm, wn, lane);

#pragma unroll
        for (int mt = 0; mt < 2; mt++) {
            int r0 = m0 + wm * 32 + mt * 16 + g;
#pragma unroll
            for (int nt = 0; nt < 8; nt++) {
                int n = n0 + wn * 64 + nt * 8 + 2 * t;
                int h = n >> 6, cc = n & 63;
                float4 c = acc[mt][nt];
                int b0r = r0 >> 11, i0r = r0 & (NN - 1);
                int b1r = (r0 + 8) >> 11, i1r = (r0 + 8) & (NN - 1);
                size_t i0 = ((size_t)(b0r * HH + h) * NN + i0r) * HD + cc;
                size_t i1 = ((size_t)(b1r * HH + h) * NN + i1r) * HD + cc;
                if (mat == 0) {
                    *(ushort2*)&g_qh[i0] = make_ushort2(h1(c.x), h1(c.y));
                    *(ushort2*)&g_qh[i1] = make_ushort2(h1(c.z), h1(c.w));
                } else {
                    u16 *Ch = (mat == 1) ? g_kh : g_vh;
                    u16 *Cl = (mat == 1) ? g_kl : g_vl;
                    u16 h0,l0,hh1,l1;
                    hsplit(c.x,h0,l0); hsplit(c.y,hh1,l1);
                    *(ushort2*)&Ch[i0] = make_ushort2(h0,hh1);
                    *(ushort2*)&Cl[i0] = make_ushort2(l0,l1);
                    hsplit(c.z,h0,l0); hsplit(c.w,hh1,l1);
                    *(ushort2*)&Ch[i1] = make_ushort2(h0,hh1);
                    *(ushort2*)&Cl[i1] = make_ushort2(l0,l1);
                }
            }
        }
    }
}

__global__ __launch_bounds__(256, 2) void gemm_out(const float* __restrict__ bias,
                                                   float* __restrict__ C)
{
    extern __shared__ char gsm[];
    const int tid = threadIdx.x, lane = tid & 31, wid = tid >> 5;
    const int g = lane >> 2, t = lane & 3;
    const int wm = wid >> 1, wn = wid & 1;
    const int m0 = blockIdx.y * 128, n0 = blockIdx.x * 128;

    float4 acc[2][8];
#pragma unroll
    for (int i = 0; i < 2; i++)
#pragma unroll
        for (int j = 0; j < 8; j++) acc[i][j] = make_float4(0.f,0.f,0.f,0.f);

    g_run(g_cth, g_wh[3], g_wl[3], gsm, m0, n0, tid, acc, wm, wn, lane);

#pragma unroll
    for (int mt = 0; mt < 2; mt++) {
        int r0 = m0 + wm * 32 + mt * 16 + g;
#pragma unroll
        for (int nt = 0; nt < 8; nt++) {
            int n = n0 + wn * 64 + nt * 8 + 2 * t;
            float bx = bias[n], by = bias[n + 1];
            float4 c = acc[mt][nt];
            *(float2*)&C[(size_t)r0 * DD + n]       = make_float2(c.x + bx, c.y + by);
            *(float2*)&C[(size_t)(r0 + 8) * DD + n] = make_float2(c.z + bx, c.w + by);
        }
    }
}

// ============================================================
// Attention (R15): S cached (log2), fixed-ref stats.
// QK = 2-term fp16 (Q single, K hi+lo). PV = 2-term fp16.
// ============================================================
#define ARS 144
#define AQPL 18432u
#define AKPL 9216u
#define AK_OFF 18432u
#define ABUF 18432u
#define ASMEM 55296
#define SCL 0.180336880f
#define LN2 0.693147181f
#define M0F 32.0f

__device__ __forceinline__ void a_issueKV(u32 bufBase, const u16* __restrict__ gh,
                                          const u16* __restrict__ gl, int row0, int tid){
#pragma unroll
    for (int i = 0; i < 4; i++) {
        int p = i >> 1;
        int rem = tid + (i & 1) * 256;
        int r = rem >> 3, c = rem & 7;
        u32 sa = bufBase + (u32)p * AKPL + (u32)(r * ARS + c * 16);
        const u16* g = p ? gl : gh;
        cpa16(sa, g + (size_t)(row0 + r) * HD + c * 8);
    }
}

__global__ __launch_bounds__(256, 2) void attn_mma(void)
{
    extern __shared__ char sm[];
    u32 sb = smem_u32(sm);

    const int tid = threadIdx.x, lane = tid & 31, wid = tid >> 5;
    const int g = lane >> 2, t = lane & 3;
    const int qt = 15 - (int)(blockIdx.x >> 5);
    const int bh = blockIdx.x & 31;
    const int h = bh >> 1, b = bh & 1;
    const int q0 = qt * 128, ktmax = 2 * qt + 1;
    const size_t ho = (size_t)(b * HH + h) * NN * HD;
    const u16 *Qh = g_qh + ho;
    const u16 *Kh = g_kh + ho, *Kl = g_kl + ho;
    const u16 *Vh = g_vh + ho, *Vl = g_vl + ho;
    float* Sc = g_s + (size_t)((b * HH + h) * 16 + qt) * 262144 + wid * 1024 + lane * 2;

    const int wr = wid * 16;
    const int gr0 = q0 + wr + g, gr1 = gr0 + 8;

    const u32 qBase = sb + (u32)((wr + (lane & 7) + 8 * ((lane >> 3) & 1)) * ARS + 16 * (lane >> 4));
    const u32 kOff = (u32)(((lane & 7) + 8 * ((lane >> 4) & 1)) * ARS + 16 * ((lane >> 3) & 1));
    const u32 vOff = (u32)(((lane & 7) + 8 * ((lane >> 3) & 1)) * ARS + 16 * (lane >> 4));

#pragma unroll
    for (int i = 0; i < 4; i++) {
        int rem = tid + i * 256;
        int r = rem >> 3, c = rem & 7;
        cpa16(sb + (u32)(r * ARS + c * 16), Qh + (size_t)(q0 + r) * HD + c * 8);
    }
    a_issueKV(sb + AK_OFF, Kh, Kl, 0, tid);
    cpa_commit();

    float mx[2] = {-1e30f, -1e30f}, se[2] = {0.f, 0.f}, st2[2] = {0.f, 0.f};

    // ===== pass A: 2-term fp16 QK, fixed-ref stats, store S =====
    for (int kt = 0; kt <= ktmax; kt++) {
        int ktb = kt * 64;
        bool act = (ktb <= q0 + wr + 15);
        cpa_wait0();
        __syncthreads();
        if (kt < ktmax) {
            a_issueKV(sb + AK_OFF + (u32)((kt + 1) & 1) * ABUF, Kh, Kl, ktb + 64, tid);
            cpa_commit();
        }
        if (act) {
            u32 kb = sb + AK_OFF + (u32)(kt & 1) * ABUF + kOff;
            float4 s[8];
#pragma unroll
            for (int nt = 0; nt < 8; nt++) s[nt] = make_float4(0.f,0.f,0.f,0.f);
#pragma unroll
            for (int kk = 0; kk < 4; kk++) {
                u32 qh4[4];
                ldmx4(qh4, qBase + (u32)(kk * 32));
#pragma unroll
                for (int ntp = 0; ntp < 4; ntp++) {
                    u32 bh4[4], bl4[4];
                    ldmx4(bh4, kb + (u32)(ntp * 2304 + kk * 32));
                    ldmx4(bl4, kb + AKPL + (u32)(ntp * 2304 + kk * 32));
                    mma2h(s[ntp*2+0], qh4, bh4, bl4, 0);
                    mma2h(s[ntp*2+1], qh4, bh4, bl4, 1);
                }
            }
            float* sp = Sc + kt * 8192;
#pragma unroll
            for (int rr = 0; rr < 2; rr++) {
                int gr = rr ? gr1 : gr0;
#pragma unroll
                for (int nt = 0; nt < 8; nt++) {
                    float x0 = rr ? s[nt].z : s[nt].x;
                    float x1 = rr ? s[nt].w : s[nt].y;
                    int gc = ktb + nt * 8 + 2 * t;
                    float sv0 = (gc     <= gr) ? x0 * SCL : -1e30f;
                    float sv1 = (gc + 1 <= gr) ? x1 * SCL : -1e30f;
                    mx[rr] = fmaxf(mx[rr], fmaxf(sv0, sv1));
                    *(float2*)&sp[(rr * 8 + nt) * 64] = make_float2(sv0, sv1);
                    float e0 = ex2f(sv0 - M0F);
                    float e1 = ex2f(sv1 - M0F);
                    se[rr] += e0 + e1;
                    st2[rr] = fmaf(e0, sv0, st2[rr]);
                    st2[rr] = fmaf(e1, sv1, st2[rr]);
                }
            }
        }
    }

    float bsc[2], bm[2], l2[2] = {0.f, 0.f};
#pragma unroll
    for (int rr = 0; rr < 2; rr++) {
        mx[rr] = fmaxf(mx[rr], __shfl_xor_sync(0xffffffffu, mx[rr], 1));
        mx[rr] = fmaxf(mx[rr], __shfl_xor_sync(0xffffffffu, mx[rr], 2));
        se[rr] += __shfl_xor_sync(0xffffffffu, se[rr], 1);
        se[rr] += __shfl_xor_sync(0xffffffffu, se[rr], 2);
        st2[rr] += __shfl_xor_sync(0xffffffffu, st2[rr], 1);
        st2[rr] += __shfl_xor_sync(0xffffffffu, st2[rr], 2);
        float ent = LN2 * (lg2f(se[rr]) + M0F - st2[rr] / se[rr]);
        float beta = 1.f;
        if (ent > 0.5f) {
            float poly = ((((-0.037f * ent + 0.481f) * ent - 2.3f) * ent + 4.917f) * ent - 1.791f);
            beta = fmaxf(poly, 1.f);
        }
        bsc[rr] = beta;
        bm[rr] = beta * mx[rr];
    }

    float4 o[8];
#pragma unroll
    for (int nt = 0; nt < 8; nt++) o[nt] = make_float4(0.f,0.f,0.f,0.f);

    __syncthreads();
    a_issueKV(sb + AK_OFF, Vh, Vl, 0, tid);
    cpa_commit();

    // ===== pass B: P (fp16) from cached S, O += P * (Vh+Vl) =====
    for (int kt = 0; kt <= ktmax; kt++) {
        int ktb = kt * 64;
        bool act = (ktb <= q0 + wr + 15);
        cpa_wait0();
        __syncthreads();
        if (kt < ktmax) {
            a_issueKV(sb + AK_OFF + (u32)((kt + 1) & 1) * ABUF, Vh, Vl, ktb + 64, tid);
            cpa_commit();
        }
        if (act) {
            u32 vb = sb + AK_OFF + (u32)(kt & 1) * ABUF + vOff;
            const float* sp = Sc + kt * 8192;
#pragma unroll
            for (int kk = 0; kk < 4; kk++) {
                u32 ah4[4];
#pragma unroll
                for (int half = 0; half < 2; half++) {
                    int nt = 2 * kk + half;
#pragma unroll
                    for (int rr = 0; rr < 2; rr++) {
                        float2 sv2 = *(const float2*)&sp[(rr * 8 + nt) * 64];
                        float p0 = ex2f(fmaf(bsc[rr], sv2.x, -bm[rr]));
                        float p1 = ex2f(fmaf(bsc[rr], sv2.y, -bm[rr]));
                        l2[rr] += p0 + p1;
                        ah4[half * 2 + rr] = packh(p0, p1);
                    }
                }
#pragma unroll
                for (int ntp = 0; ntp < 4; ntp++) {
                    u32 vh4[4], vl4[4];
                    ldmx4t(vh4, vb + (u32)(kk * 2304 + ntp * 32));
                    ldmx4t(vl4, vb + AKPL + (u32)(kk * 2304 + ntp * 32));
                    mma2h(o[ntp*2+0], ah4, vh4, vl4, 0);
                    mma2h(o[ntp*2+1], ah4, vh4, vl4, 1);
                }
            }
        }
    }

#pragma unroll
    for (int rr = 0; rr < 2; rr++) {
        l2[rr] += __shfl_xor_sync(0xffffffffu, l2[rr], 1);
        l2[rr] += __shfl_xor_sync(0xffffffffu, l2[rr], 2);
    }
    float inv0 = 1.f / l2[0], inv1 = 1.f / l2[1];
    size_t row0 = ((size_t)(b * NN) + gr0) * DD + h * HD;
    size_t row1 = ((size_t)(b * NN) + gr1) * DD + h * HD;
#pragma unroll
    for (int nt = 0; nt < 8; nt++) {
        int c = nt * 8 + 2 * t;
        *(ushort2*)&g_cth[row0 + c] = make_ushort2(h1(o[nt].x * inv0), h1(o[nt].y * inv0));
        *(ushort2*)&g_cth[row1 + c] = make_ushort2(h1(o[nt].z * inv1), h1(o[nt].w * inv1));
    }
}

// ============================================================
extern "C" void kernel_launch(void* const* d_in, const int* in_sizes, int n_in,
                              void* d_out, int out_size)
{
    const float* x  = (const float*)d_in[0];
    const float* Wq = (const float*)d_in[1];
    const float* Wk = (const float*)d_in[2];
    const float* Wv = (const float*)d_in[3];
    const float* Wo = (const float*)d_in[4];
    const float* bo = (const float*)d_in[5];
    float* out = (float*)d_out;

    const int gsmem = 3 * (int)GSTG;   // 73728
    cudaFuncSetAttribute(gemm_qkv, cudaFuncAttributeMaxDynamicSharedMemorySize, gsmem);
    cudaFuncSetAttribute(gemm_out, cudaFuncAttributeMaxDynamicSharedMemorySize, gsmem);
    cudaFuncSetAttribute(attn_mma, cudaFuncAttributeMaxDynamicSharedMemorySize, ASMEM);

    presplitAll<<<8192, 256>>>((const float4*)x, (const float4*)Wq, (const float4*)Wk,
                               (const float4*)Wv, (const float4*)Wo);

    gemm_qkv<<<296, 256, gsmem>>>();

    attn_mma<<<512, 256, ASMEM>>>();

    dim3 og(8, 32);
    gemm_out<<<og, 256, gsmem>>>(bo, out);
}

// round 17
// speedup vs baseline: 1.3996x; 1.0161x over previous
#include <cuda_runtime.h>
#include <cstdint>

#define BB 2
#define NN 2048
#define DD 1024
#define HH 16
#define HD 64
typedef unsigned short u16;
typedef uint32_t u32;

__device__ __align__(16) u16 g_xh[(size_t)BB*NN*DD];          // fp16 single plane
__device__ __align__(16) u16 g_wh[4][(size_t)DD*DD];          // fp16 hi
__device__ __align__(16) u16 g_wl[4][(size_t)DD*DD];          // fp16 lo
__device__ __align__(16) u16 g_qh[(size_t)BB*HH*NN*HD];       // fp16 single plane
__device__ __align__(16) u16 g_kh[(size_t)BB*HH*NN*HD];
__device__ __align__(16) u16 g_kl[(size_t)BB*HH*NN*HD];
__device__ __align__(16) u16 g_vh[(size_t)BB*HH*NN*HD];
__device__ __align__(16) u16 g_vl[(size_t)BB*HH*NN*HD];
__device__ __align__(16) u16 g_cth[(size_t)BB*NN*DD];         // ctx fp16 single plane
__device__ float g_s[(size_t)512*262144];

__device__ __forceinline__ void hsplit(float x, u16 &h, u16 &l){
    asm("cvt.rn.f16.f32 %0, %1;" : "=h"(h) : "f"(x));
    float hf; asm("cvt.f32.f16 %0, %1;" : "=f"(hf) : "h"(h));
    asm("cvt.rn.f16.f32 %0, %1;" : "=h"(l) : "f"(x - hf));
}
__device__ __forceinline__ u16 h1(float x){
    u16 h; asm("cvt.rn.f16.f32 %0, %1;" : "=h"(h) : "f"(x));
    return h;
}
__device__ __forceinline__ u32 packh(float lo, float hi){
    u32 r; asm("cvt.rn.f16x2.f32 %0, %1, %2;" : "=r"(r) : "f"(hi), "f"(lo));
    return r;
}
__device__ __forceinline__ float ex2f(float x){
    float r; asm("ex2.approx.ftz.f32 %0, %1;" : "=f"(r) : "f"(x));
    return r;
}
__device__ __forceinline__ float lg2f(float x){
    float r; asm("lg2.approx.ftz.f32 %0, %1;" : "=f"(r) : "f"(x));
    return r;
}
__device__ __forceinline__ u32 smem_u32(const void* p){
    u32 a;
    asm("{ .reg .u64 t; cvta.to.shared.u64 t, %1; cvt.u32.u64 %0, t; }" : "=r"(a) : "l"(p));
    return a;
}
__device__ __forceinline__ void cpa16(u32 dst, const void* src){
    asm volatile("cp.async.cg.shared.global [%0], [%1], 16;" :: "r"(dst), "l"(src));
}
__device__ __forceinline__ void cpa_commit(){ asm volatile("cp.async.commit_group;" ::: "memory"); }
__device__ __forceinline__ void cpa_wait0(){ asm volatile("cp.async.wait_group 0;" ::: "memory"); }
__device__ __forceinline__ void cpa_wait1(){ asm volatile("cp.async.wait_group 1;" ::: "memory"); }
__device__ __forceinline__ void cpa_wait2(){ asm volatile("cp.async.wait_group 2;" ::: "memory"); }

__device__ __forceinline__ void ldmx4(u32* r, u32 a){
    asm volatile("ldmatrix.sync.aligned.m8n8.x4.shared.b16 {%0,%1,%2,%3}, [%4];"
        : "=r"(r[0]), "=r"(r[1]), "=r"(r[2]), "=r"(r[3]) : "r"(a));
}
__device__ __forceinline__ void ldmx4t(u32* r, u32 a){
    asm volatile("ldmatrix.sync.aligned.m8n8.x4.trans.shared.b16 {%0,%1,%2,%3}, [%4];"
        : "=r"(r[0]), "=r"(r[1]), "=r"(r[2]), "=r"(r[3]) : "r"(a));
}
__device__ __forceinline__ void mmah(float4& d, const u32* a, u32 b0, u32 b1){
    asm volatile("mma.sync.aligned.m16n8k16.row.col.f32.f16.f16.f32 "
        "{%0,%1,%2,%3},{%4,%5,%6,%7},{%8,%9},{%0,%1,%2,%3};"
        : "+f"(d.x), "+f"(d.y), "+f"(d.z), "+f"(d.w)
        : "r"(a[0]), "r"(a[1]), "r"(a[2]), "r"(a[3]), "r"(b0), "r"(b1));
}
__device__ __forceinline__ void mma2h(float4& d, const u32* ah,
                                      const u32* bh, const u32* bl, int ng){
    mmah(d, ah, bh[2*ng], bh[2*ng+1]);
    mmah(d, ah, bl[2*ng], bl[2*ng+1]);
}

// ============================================================
// presplit: x fp16 single; W fp16 hi/lo. Single launch.
// ============================================================
__global__ __launch_bounds__(256) void presplitAll(const float4* __restrict__ x,
                                                   const float4* __restrict__ Wq,
                                                   const float4* __restrict__ Wk,
                                                   const float4* __restrict__ Wv,
                                                   const float4* __restrict__ Wo){
    int bid = blockIdx.x;
    if (bid < 4096) {
        int i = bid * 256 + threadIdx.x;
        float4 v = x[i];
        ((ushort4*)g_xh)[i] = make_ushort4(h1(v.x), h1(v.y), h1(v.z), h1(v.w));
    } else {
        int m = (bid - 4096) >> 10;
        int i = ((bid - 4096) & 1023) * 256 + threadIdx.x;
        const float4* src = (m == 0) ? Wq : (m == 1) ? Wk : (m == 2) ? Wv : Wo;
        float4 v = src[i];
        u16 h0,l0,hh1,l1,h2,l2,h3,l3;
        hsplit(v.x,h0,l0); hsplit(v.y,hh1,l1); hsplit(v.z,h2,l2); hsplit(v.w,h3,l3);
        ((ushort4*)g_wh[m])[i] = make_ushort4(h0,hh1,h2,h3);
        ((ushort4*)g_wl[m])[i] = make_ushort4(l0,l1,l2,l3);
    }
}

// ============================================================
// GEMM: 128x128 tile, BK=32, fp16 2-term, SW64 rows, 4-stage.
// ============================================================
#define GPL 8192u
#define GSTG 24576u

__device__ __forceinline__ void g_issue(u32 st,
        const u16* __restrict__ Ah,
        const u16* __restrict__ Bh, const u16* __restrict__ Bl,
        int m0, int n0, int k0, int tid){
#pragma unroll
    for (int i = 0; i < 6; i++) {
        int idx = tid + i * 256;
        int p = idx >> 9, q = idx & 511;
        int r = q >> 2, c = q & 3;
        u32 sa = st + (u32)p * GPL + (u32)(r * 64 + ((c * 16) ^ (((r >> 1) & 3) << 4)));
        const u16* g = (p == 0) ? Ah : (p == 1) ? Bh : Bl;
        int rb = (p == 0) ? m0 : n0;
        cpa16(sa, g + (size_t)(rb + r) * DD + k0 + c * 8);
    }
}

__device__ __forceinline__ void g_run(const u16* Ah, const u16* Bh, const u16* Bl,
                                      char* sm, int m0, int n0, int tid,
                                      float4 (&acc)[2][8], int wm, int wn, int lane){
    u32 sb = smem_u32(sm);
    const int arow = wm * 32 + (lane & 7) + 8 * ((lane >> 3) & 1);
    const int brow = wn * 64 + (lane & 7) + 8 * ((lane >> 4) & 1);
    const u32 axm = ((((lane & 7) >> 1) & 3) << 4);
    const u32 aB = sb + (u32)(arow * 64);
    const u32 bB = sb + GPL + (u32)(brow * 64);
    const u32 a16 = 16u * (u32)(lane >> 4);
    const u32 b16 = 16u * (u32)((lane >> 3) & 1);

    g_issue(sb,             Ah, Bh, Bl, m0, n0, 0,  tid); cpa_commit();
    g_issue(sb + GSTG,      Ah, Bh, Bl, m0, n0, 32, tid); cpa_commit();
    g_issue(sb + 2u * GSTG, Ah, Bh, Bl, m0, n0, 64, tid); cpa_commit();
    for (int it = 0; it < 32; it++) {
        u32 so = (u32)(it & 3) * GSTG;
        if (it < 30) cpa_wait2();
        else if (it == 30) cpa_wait1();
        else cpa_wait0();
        __syncthreads();
        if (it + 3 < 32) {
            g_issue(sb + (u32)((it + 3) & 3) * GSTG, Ah, Bh, Bl, m0, n0, (it + 3) * 32, tid);
            cpa_commit();
        }
#pragma unroll
        for (int kk = 0; kk < 2; kk++) {
            u32 ah4[2][4];
            u32 ao = ((u32)(kk * 32) + a16) ^ axm;
#pragma unroll
            for (int mt = 0; mt < 2; mt++)
                ldmx4(ah4[mt], aB + so + (u32)(mt * 1024) + ao);
            u32 bo = ((u32)(kk * 32) + b16) ^ axm;
#pragma unroll
            for (int ntp = 0; ntp < 4; ntp++) {
                u32 bh4[4], bl4[4];
                ldmx4(bh4, bB + so + (u32)(ntp * 1024) + bo);
                ldmx4(bl4, bB + so + GPL + (u32)(ntp * 1024) + bo);
#pragma unroll
                for (int mt = 0; mt < 2; mt++) {
                    mma2h(acc[mt][ntp*2+0], ah4[mt], bh4, bl4, 0);
                    mma2h(acc[mt][ntp*2+1], ah4[mt], bh4, bl4, 1);
                }
            }
        }
    }
}

// persistent QKV: grid = 296, stride loop over 768 tiles
__global__ __launch_bounds__(256, 2) void gemm_qkv(void)
{
    extern __shared__ char gsm[];
    const int tid = threadIdx.x, lane = tid & 31, wid = tid >> 5;
    const int g = lane >> 2, t = lane & 3;
    const int wm = wid >> 1, wn = wid & 1;

    for (int tile = blockIdx.x; tile < 768; tile += gridDim.x) {
        const int mat = tile >> 8, rem = tile & 255;
        const int m0 = (rem >> 3) * 128, n0 = (rem & 7) * 128;

        float4 acc[2][8];
#pragma unroll
        for (int i = 0; i < 2; i++)
#pragma unroll
            for (int j = 0; j < 8; j++) acc[i][j] = make_float4(0.f,0.f,0.f,0.f);

        __syncthreads();
        g_run(g_xh, g_wh[mat], g_wl[mat], gsm, m0, n0, tid, acc, wm, wn, lane);

#pragma unroll
        for (int mt = 0; mt < 2; mt++) {
            int r0 = m0 + wm * 32 + mt * 16 + g;
#pragma unroll
            for (int nt = 0; nt < 8; nt++) {
                int n = n0 + wn * 64 + nt * 8 + 2 * t;
                int h = n >> 6, cc = n & 63;
                float4 c = acc[mt][nt];
                int b0r = r0 >> 11, i0r = r0 & (NN - 1);
                int b1r = (r0 + 8) >> 11, i1r = (r0 + 8) & (NN - 1);
                size_t i0 = ((size_t)(b0r * HH + h) * NN + i0r) * HD + cc;
                size_t i1 = ((size_t)(b1r * HH + h) * NN + i1r) * HD + cc;
                if (mat == 0) {
                    *(ushort2*)&g_qh[i0] = make_ushort2(h1(c.x), h1(c.y));
                    *(ushort2*)&g_qh[i1] = make_ushort2(h1(c.z), h1(c.w));
                } else {
                    u16 *Ch = (mat == 1) ? g_kh : g_vh;
                    u16 *Cl = (mat == 1) ? g_kl : g_vl;
                    u16 h0,l0,hh1,l1;
                    hsplit(c.x,h0,l0); hsplit(c.y,hh1,l1);
                    *(ushort2*)&Ch[i0] = make_ushort2(h0,hh1);
                    *(ushort2*)&Cl[i0] = make_ushort2(l0,l1);
                    hsplit(c.z,h0,l0); hsplit(c.w,hh1,l1);
                    *(ushort2*)&Ch[i1] = make_ushort2(h0,hh1);
                    *(ushort2*)&Cl[i1] = make_ushort2(l0,l1);
                }
            }
        }
    }
}

__global__ __launch_bounds__(256, 2) void gemm_out(const float* __restrict__ bias,
                                                   float* __restrict__ C)
{
    extern __shared__ char gsm[];
    const int tid = threadIdx.x, lane = tid & 31, wid = tid >> 5;
    const int g = lane >> 2, t = lane & 3;
    const int wm = wid >> 1, wn = wid & 1;
    const int m0 = blockIdx.y * 128, n0 = blockIdx.x * 128;

    float4 acc[2][8];
#pragma unroll
    for (int i = 0; i < 2; i++)
#pragma unroll
        for (int j = 0; j < 8; j++) acc[i][j] = make_float4(0.f,0.f,0.f,0.f);

    g_run(g_cth, g_wh[3], g_wl[3], gsm, m0, n0, tid, acc, wm, wn, lane);

#pragma unroll
    for (int mt = 0; mt < 2; mt++) {
        int r0 = m0 + wm * 32 + mt * 16 + g;
#pragma unroll
        for (int nt = 0; nt < 8; nt++) {
            int n = n0 + wn * 64 + nt * 8 + 2 * t;
            float bx = bias[n], by = bias[n + 1];
            float4 c = acc[mt][nt];
            *(float2*)&C[(size_t)r0 * DD + n]       = make_float2(c.x + bx, c.y + by);
            *(float2*)&C[(size_t)(r0 + 8) * DD + n] = make_float2(c.z + bx, c.w + by);
        }
    }
}

// ============================================================
// Attention: S cached (log2), fixed-ref stats, fp16 2-term QK/PV.
// Key tiles of 128 (one load/barrier), computed as two 64-halves.
// ============================================================
#define ARS 144
#define AKPL 18432u      // one 128-row plane
#define AK_OFF 18432u    // after Q
#define ABUF 36864u      // hi+lo
#define ASMEM 92160
#define SCL 0.180336880f
#define LN2 0.693147181f
#define M0F 32.0f

__device__ __forceinline__ void a_issueKV(u32 bufBase, const u16* __restrict__ gh,
                                          const u16* __restrict__ gl, int row0, int tid){
#pragma unroll
    for (int i = 0; i < 8; i++) {
        int idx = tid + i * 256;
        int p = idx >> 10, q = idx & 1023;
        int r = q >> 3, c = q & 7;
        u32 sa = bufBase + (u32)p * AKPL + (u32)(r * ARS + c * 16);
        const u16* g = p ? gl : gh;
        cpa16(sa, g + (size_t)(row0 + r) * HD + c * 8);
    }
}

__global__ __launch_bounds__(256, 2) void attn_mma(void)
{
    extern __shared__ char sm[];
    u32 sb = smem_u32(sm);

    const int tid = threadIdx.x, lane = tid & 31, wid = tid >> 5;
    const int g = lane >> 2, t = lane & 3;
    const int qt = 15 - (int)(blockIdx.x >> 5);
    const int bh = blockIdx.x & 31;
    const int h = bh >> 1, b = bh & 1;
    const int q0 = qt * 128;
    const size_t ho = (size_t)(b * HH + h) * NN * HD;
    const u16 *Qh = g_qh + ho;
    const u16 *Kh = g_kh + ho, *Kl = g_kl + ho;
    const u16 *Vh = g_vh + ho, *Vl = g_vl + ho;
    float* Sc = g_s + (size_t)((b * HH + h) * 16 + qt) * 262144 + wid * 1024 + lane * 2;

    const int wr = wid * 16;
    const int gr0 = q0 + wr + g, gr1 = gr0 + 8;

    const u32 qBase = sb + (u32)((wr + (lane & 7) + 8 * ((lane >> 3) & 1)) * ARS + 16 * (lane >> 4));
    const u32 kOff = (u32)(((lane & 7) + 8 * ((lane >> 4) & 1)) * ARS + 16 * ((lane >> 3) & 1));
    const u32 vOff = (u32)(((lane & 7) + 8 * ((lane >> 3) & 1)) * ARS + 16 * (lane >> 4));

    // Q tile: single fp16 plane
#pragma unroll
    for (int i = 0; i < 4; i++) {
        int rem = tid + i * 256;
        int r = rem >> 3, c = rem & 7;
        cpa16(sb + (u32)(r * ARS + c * 16), Qh + (size_t)(q0 + r) * HD + c * 8);
    }
    a_issueKV(sb + AK_OFF, Kh, Kl, 0, tid);
    cpa_commit();

    float mx[2] = {-1e30f, -1e30f}, se[2] = {0.f, 0.f}, st2[2] = {0.f, 0.f};

    // ===== pass A: K tiles of 128, two 64-halves each =====
    for (int kt = 0; kt <= qt; kt++) {
        cpa_wait0();
        __syncthreads();
        if (kt < qt) {
            a_issueKV(sb + AK_OFF + (u32)((kt + 1) & 1) * ABUF, Kh, Kl, (kt + 1) * 128, tid);
            cpa_commit();
        }
        u32 kb0 = sb + AK_OFF + (u32)(kt & 1) * ABUF + kOff;
#pragma unroll
        for (int half = 0; half < 2; half++) {
            int ktb = kt * 128 + half * 64;
            if (ktb > q0 + wr + 15) continue;
            u32 kb = kb0 + (u32)(half * 9216);
            float4 s[8];
#pragma unroll
            for (int nt = 0; nt < 8; nt++) s[nt] = make_float4(0.f,0.f,0.f,0.f);
#pragma unroll
            for (int kk = 0; kk < 4; kk++) {
                u32 qh4[4];
                ldmx4(qh4, qBase + (u32)(kk * 32));
#pragma unroll
                for (int ntp = 0; ntp < 4; ntp++) {
                    u32 bh4[4], bl4[4];
                    ldmx4(bh4, kb + (u32)(ntp * 2304 + kk * 32));
                    ldmx4(bl4, kb + AKPL + (u32)(ntp * 2304 + kk * 32));
                    mma2h(s[ntp*2+0], qh4, bh4, bl4, 0);
                    mma2h(s[ntp*2+1], qh4, bh4, bl4, 1);
                }
            }
            float* sp = Sc + (kt * 2 + half) * 8192;
#pragma unroll
            for (int rr = 0; rr < 2; rr++) {
                int gr = rr ? gr1 : gr0;
#pragma unroll
                for (int nt = 0; nt < 8; nt++) {
                    float x0 = rr ? s[nt].z : s[nt].x;
                    float x1 = rr ? s[nt].w : s[nt].y;
                    int gc = ktb + nt * 8 + 2 * t;
                    float sv0 = (gc     <= gr) ? x0 * SCL : -1e30f;
                    float sv1 = (gc + 1 <= gr) ? x1 * SCL : -1e30f;
                    mx[rr] = fmaxf(mx[rr], fmaxf(sv0, sv1));
                    *(float2*)&sp[(rr * 8 + nt) * 64] = make_float2(sv0, sv1);
                    float e0 = ex2f(sv0 - M0F);
                    float e1 = ex2f(sv1 - M0F);
                    se[rr] += e0 + e1;
                    st2[rr] = fmaf(e0, sv0, st2[rr]);
                    st2[rr] = fmaf(e1, sv1, st2[rr]);
                }
            }
        }
    }

    float bsc[2], bm[2], l2[2] = {0.f, 0.f};
#pragma unroll
    for (int rr = 0; rr < 2; rr++) {
        mx[rr] = fmaxf(mx[rr], __shfl_xor_sync(0xffffffffu, mx[rr], 1));
        mx[rr] = fmaxf(mx[rr], __shfl_xor_sync(0xffffffffu, mx[rr], 2));
        se[rr] += __shfl_xor_sync(0xffffffffu, se[rr], 1);
        se[rr] += __shfl_xor_sync(0xffffffffu, se[rr], 2);
        st2[rr] += __shfl_xor_sync(0xffffffffu, st2[rr], 1);
        st2[rr] += __shfl_xor_sync(0xffffffffu, st2[rr], 2);
        float ent = LN2 * (lg2f(se[rr]) + M0F - st2[rr] / se[rr]);
        float beta = 1.f;
        if (ent > 0.5f) {
            float poly = ((((-0.037f * ent + 0.481f) * ent - 2.3f) * ent + 4.917f) * ent - 1.791f);
            beta = fmaxf(poly, 1.f);
        }
        bsc[rr] = beta;
        bm[rr] = beta * mx[rr];
    }

    float4 o[8];
#pragma unroll
    for (int nt = 0; nt < 8; nt++) o[nt] = make_float4(0.f,0.f,0.f,0.f);

    __syncthreads();
    a_issueKV(sb + AK_OFF, Vh, Vl, 0, tid);
    cpa_commit();

    // ===== pass B: V tiles of 128, P (fp16) from cached S =====
    for (int kt = 0; kt <= qt; kt++) {
        cpa_wait0();
        __syncthreads();
        if (kt < qt) {
            a_issueKV(sb + AK_OFF + (u32)((kt + 1) & 1) * ABUF, Vh, Vl, (kt + 1) * 128, tid);
            cpa_commit();
        }
        u32 vb0 = sb + AK_OFF + (u32)(kt & 1) * ABUF + vOff;
#pragma unroll
        for (int half = 0; half < 2; half++) {
            int ktb = kt * 128 + half * 64;
            if (ktb > q0 + wr + 15) continue;
            u32 vb = vb0 + (u32)(half * 9216);
            const float* sp = Sc + (kt * 2 + half) * 8192;
#pragma unroll
            for (int kk = 0; kk < 4; kk++) {
                u32 ah4[4];
#pragma unroll
                for (int hlf = 0; hlf < 2; hlf++) {
                    int nt = 2 * kk + hlf;
#pragma unroll
                    for (int rr = 0; rr < 2; rr++) {
                        float2 sv2 = *(const float2*)&sp[(rr * 8 + nt) * 64];
                        float p0 = ex2f(fmaf(bsc[rr], sv2.x, -bm[rr]));
                        float p1 = ex2f(fmaf(bsc[rr], sv2.y, -bm[rr]));
                        l2[rr] += p0 + p1;
                        ah4[hlf * 2 + rr] = packh(p0, p1);
                    }
                }
#pragma unroll
                for (int ntp = 0; ntp < 4; ntp++) {
                    u32 vh4[4], vl4[4];
                    ldmx4t(vh4, vb + (u32)(kk * 2304 + ntp * 32));
                    ldmx4t(vl4, vb + AKPL + (u32)(kk * 2304 + ntp * 32));
                    mma2h(o[ntp*2+0], ah4, vh4, vl4, 0);
                    mma2h(o[ntp*2+1], ah4, vh4, vl4, 1);
                }
            }
        }
    }

#pragma unroll
    for (int rr = 0; rr < 2; rr++) {
        l2[rr] += __shfl_xor_sync(0xffffffffu, l2[rr], 1);
        l2[rr] += __shfl_xor_sync(0xffffffffu, l2[rr], 2);
    }
    float inv0 = 1.f / l2[0], inv1 = 1.f / l2[1];
    size_t row0 = ((size_t)(b * NN) + gr0) * DD + h * HD;
    size_t row1 = ((size_t)(b * NN) + gr1) * DD + h * HD;
#pragma unroll
    for (int nt = 0; nt < 8; nt++) {
        int c = nt * 8 + 2 * t;
        *(ushort2*)&g_cth[row0 + c] = make_ushort2(h1(o[nt].x * inv0), h1(o[nt].y * inv0));
        *(ushort2*)&g_cth[row1 + c] = make_ushort2(h1(o[nt].z * inv1), h1(o[nt].w * inv1));
    }
}

// ============================================================
extern "C" void kernel_launch(void* const* d_in, const int* in_sizes, int n_in,
                              void* d_out, int out_size)
{
    const float* x  = (const float*)d_in[0];
    const float* Wq = (const float*)d_in[1];
    const float* Wk = (const float*)d_in[2];
    const float* Wv = (const float*)d_in[3];
    const float* Wo = (const float*)d_in[4];
    const float* bo = (const float*)d_in[5];
    float* out = (float*)d_out;

    const int gsmem = 4 * (int)GSTG;   // 98304
    cudaFuncSetAttribute(gemm_qkv, cudaFuncAttributeMaxDynamicSharedMemorySize, gsmem);
    cudaFuncSetAttribute(gemm_out, cudaFuncAttributeMaxDynamicSharedMemorySize, gsmem);
    cudaFuncSetAttribute(attn_mma, cudaFuncAttributeMaxDynamicSharedMemorySize, ASMEM);

    presplitAll<<<8192, 256>>>((const float4*)x, (const float4*)Wq, (const float4*)Wk,
                               (const float4*)Wv, (const float4*)Wo);

    gemm_qkv<<<296, 256, gsmem>>>();

    attn_mma<<<512, 256, ASMEM>>>();

    dim3 og(8, 32);
    gemm_out<<<og, 256, gsmem>>>(bo, out);
}